// round 13
// baseline (speedup 1.0000x reference)
#include <cuda_runtime.h>
#include <cuda_bf16.h>
#include <cuda_fp16.h>
#include <math.h>
#include <stdint.h>

// ---------------- problem constants ----------------
#define D_MODEL 256
#define D_FFN   1024
#define LQ      21760
#define BATCH   2
#define M_ROWS  (BATCH * LQ)   // 43520

__device__ __constant__ int c_ST[4] = {0, 16384, 20480, 21504};

// ---------------- scratch ----------------
__device__ __nv_bfloat16 g_srcb [(size_t)M_ROWS * D_MODEL];
__device__ __nv_bfloat16 g_qsumb[(size_t)M_ROWS * D_MODEL];
__device__ __nv_bfloat16 g_value[(size_t)M_ROWS * D_MODEL];
__device__ float g_oa   [(size_t)M_ROWS * 384];   // oa; later reused as t1 (M*256 fp32)
__device__ __nv_bfloat16 g_samp [(size_t)M_ROWS * D_MODEL];
__device__ float g_h    [(size_t)M_ROWS * D_MODEL];
__device__ __nv_bfloat16 g_hb   [(size_t)M_ROWS * D_MODEL];
__device__ __nv_bfloat16 g_ffn  [(size_t)M_ROWS * D_FFN];
__device__ float g_t2   [(size_t)M_ROWS * D_MODEL];
__device__ __nv_bfloat16 g_WvalT [256 * 256];
__device__ __nv_bfloat16 g_WoaT  [384 * 256];
__device__ __nv_bfloat16 g_WoutT [256 * 256];
__device__ __nv_bfloat16 g_W1T   [1024 * 256];
__device__ __nv_bfloat16 g_W2T   [256 * 1024];

// ---------------- helpers ----------------
__device__ __forceinline__ uint32_t smem_u32(const void* p) {
    uint32_t a;
    asm("{ .reg .u64 t; cvta.to.shared.u64 t, %1; cvt.u32.u64 %0, t; }" : "=r"(a) : "l"(p));
    return a;
}
__device__ __forceinline__ void cpasync16(uint32_t dst, const void* src) {
    asm volatile("cp.async.cg.shared.global [%0], [%1], 16;" :: "r"(dst), "l"(src));
}
__device__ __forceinline__ void ldsm_x4(uint32_t& r0, uint32_t& r1, uint32_t& r2, uint32_t& r3, uint32_t addr) {
    asm volatile("ldmatrix.sync.aligned.m8n8.x4.shared.b16 {%0,%1,%2,%3}, [%4];"
        : "=r"(r0), "=r"(r1), "=r"(r2), "=r"(r3) : "r"(addr));
}
__device__ __forceinline__ void mma_bf16(float* d, const uint32_t* a, const uint32_t* b) {
    asm volatile("mma.sync.aligned.m16n8k16.row.col.f32.bf16.bf16.f32 "
        "{%0,%1,%2,%3}, {%4,%5,%6,%7}, {%8,%9}, {%0,%1,%2,%3};"
        : "+f"(d[0]), "+f"(d[1]), "+f"(d[2]), "+f"(d[3])
        : "r"(a[0]), "r"(a[1]), "r"(a[2]), "r"(a[3]), "r"(b[0]), "r"(b[1]));
}

// ---------------- shared GEMM core: 128x128 tile, BK=64, 3-stage ----------------
__device__ __forceinline__ void gemm_core(
    const __nv_bfloat16* __restrict__ A, const __nv_bfloat16* __restrict__ WT,
    const float* __restrict__ bias, const float* __restrict__ bias2, int nsplit,
    const float* __restrict__ res, void* __restrict__ Cout,
    bool relu, bool bf16out, int N, int K, int bm, int bn, uint32_t smBase)
{
    const int tid = threadIdx.x;
    const int lane = tid & 31;
    const int wid = tid >> 5;
    const int wm = wid & 1;
    const int wn = wid >> 1;

    const __nv_bfloat16* aG[4]; const __nv_bfloat16* bG[4];
    uint32_t sOff[4];
#pragma unroll
    for (int i = 0; i < 4; i++) {
        const int id = tid + i * 256;
        const int row = id >> 3, ck = id & 7;
        aG[i] = A  + (size_t)(bm + row) * K + ck * 8;
        bG[i] = WT + (size_t)(bn + row) * K + ck * 8;
        sOff[i] = row * 128 + ((ck ^ (row & 7)) * 16);
    }

    const int aRow = wm * 64 + (lane & 15);
    const int aCkH = lane >> 4;
    const int bRow = wn * 32 + ((lane >> 4) & 1) * 8 + (lane & 7);
    const int bCkH = (lane >> 3) & 1;

    float acc[4][4][4];
#pragma unroll
    for (int i = 0; i < 4; i++)
#pragma unroll
        for (int j = 0; j < 4; j++)
#pragma unroll
            for (int k = 0; k < 4; k++) acc[i][j][k] = 0.f;

    const int Cs = K >> 6;

#pragma unroll
    for (int i = 0; i < 4; i++) {
        cpasync16(smBase + sOff[i], aG[i]);
        cpasync16(smBase + 16384 + sOff[i], bG[i]);
    }
    asm volatile("cp.async.commit_group;" ::: "memory");
#pragma unroll
    for (int i = 0; i < 4; i++) {
        cpasync16(smBase + 32768 + sOff[i], aG[i] + 64);
        cpasync16(smBase + 32768 + 16384 + sOff[i], bG[i] + 64);
    }
    asm volatile("cp.async.commit_group;" ::: "memory");

    int st = 0, ldst = 2;
    for (int c = 0; c < Cs; ++c) {
        if (c == Cs - 1) asm volatile("cp.async.wait_group 0;" ::: "memory");
        else             asm volatile("cp.async.wait_group 1;" ::: "memory");
        __syncthreads();

        const uint32_t sA = smBase + (uint32_t)st * 32768;
        const uint32_t sB = sA + 16384;

#pragma unroll
        for (int ks = 0; ks < 4; ks++) {
            uint32_t af[4][4];
            uint32_t bfr[2][4];
#pragma unroll
            for (int mt = 0; mt < 4; mt++) {
                const int row = aRow + mt * 16;
                const int ck = ks * 2 + aCkH;
                ldsm_x4(af[mt][0], af[mt][1], af[mt][2], af[mt][3],
                        sA + row * 128 + ((ck ^ (row & 7)) * 16));
            }
#pragma unroll
            for (int np = 0; np < 2; np++) {
                const int row = bRow + np * 16;
                const int ck = ks * 2 + bCkH;
                ldsm_x4(bfr[np][0], bfr[np][1], bfr[np][2], bfr[np][3],
                        sB + row * 128 + ((ck ^ (row & 7)) * 16));
            }
#pragma unroll
            for (int mt = 0; mt < 4; mt++)
#pragma unroll
                for (int nt = 0; nt < 4; nt++)
                    mma_bf16(acc[mt][nt], af[mt], &bfr[nt >> 1][(nt & 1) * 2]);
        }

        if (c + 2 < Cs) {
            const int k0 = (c + 2) << 6;
            const uint32_t dA = smBase + (uint32_t)ldst * 32768;
#pragma unroll
            for (int i = 0; i < 4; i++) {
                cpasync16(dA + sOff[i], aG[i] + k0);
                cpasync16(dA + 16384 + sOff[i], bG[i] + k0);
            }
            asm volatile("cp.async.commit_group;" ::: "memory");
        }
        st = (st == 2) ? 0 : st + 1;
        ldst = (ldst == 2) ? 0 : ldst + 1;
    }

    const int r0base = bm + wm * 64 + (lane >> 2);
    const int cbase  = bn + wn * 32 + (lane & 3) * 2;
#pragma unroll
    for (int mt = 0; mt < 4; mt++) {
#pragma unroll
        for (int nt = 0; nt < 4; nt++) {
            const int col = cbase + nt * 8;
            const float bx = (col < nsplit) ? bias[col] : bias2[col - nsplit];
            const float by = (col + 1 < nsplit) ? bias[col + 1] : bias2[col + 1 - nsplit];
#pragma unroll
            for (int half = 0; half < 2; half++) {
                const int row = r0base + mt * 16 + half * 8;
                float vx = acc[mt][nt][half * 2 + 0] + bx;
                float vy = acc[mt][nt][half * 2 + 1] + by;
                if (res) {
                    const float* rp = res + (size_t)row * N + col;
                    vx += rp[0]; vy += rp[1];
                }
                if (relu) { vx = fmaxf(vx, 0.f); vy = fmaxf(vy, 0.f); }
                if (bf16out) {
                    __nv_bfloat162 bb = __floats2bfloat162_rn(vx, vy);
                    *(__nv_bfloat162*)((__nv_bfloat16*)Cout + (size_t)row * N + col) = bb;
                } else {
                    *(float2*)((float*)Cout + (size_t)row * N + col) = make_float2(vx, vy);
                }
            }
        }
    }
}

// merged value + oa projection GEMM: grid (5, MT). bx<2 -> value, else oa.
__global__ void __launch_bounds__(256) gemm_proj(
    const __nv_bfloat16* __restrict__ srcb, const __nv_bfloat16* __restrict__ qsumb,
    const __nv_bfloat16* __restrict__ WvalT, const __nv_bfloat16* __restrict__ WoaT,
    const float* __restrict__ b_val, const float* __restrict__ b_off,
    const float* __restrict__ b_attn,
    __nv_bfloat16* __restrict__ value, float* __restrict__ oa)
{
    extern __shared__ char dynsm[];
    const uint32_t smBase = smem_u32(dynsm);
    const int bm = blockIdx.y * 128;
    if (blockIdx.x < 2) {
        gemm_core(srcb, WvalT, b_val, b_val, 1 << 30, nullptr, value,
                  false, true, 256, 256, bm, blockIdx.x * 128, smBase);
    } else {
        gemm_core(qsumb, WoaT, b_off, b_attn, 256, nullptr, oa,
                  false, false, 384, 256, bm, (blockIdx.x - 2) * 128, smBase);
    }
}

// residual GEMM: C(fp32) = A @ W + bias + res
__global__ void __launch_bounds__(256) gemm_res(
    const __nv_bfloat16* __restrict__ A, const __nv_bfloat16* __restrict__ WT,
    const float* __restrict__ bias, const float* __restrict__ res,
    float* __restrict__ C, int K)
{
    extern __shared__ char dynsm[];
    const uint32_t smBase = smem_u32(dynsm);
    gemm_core(A, WT, bias, bias, 1 << 30, res, C,
              false, false, 256, K, blockIdx.y * 128, blockIdx.x * 128, smBase);
}

// ffn GEMM: relu + bf16 out
__global__ void __launch_bounds__(256) gemm_ffn(
    const __nv_bfloat16* __restrict__ hb, const __nv_bfloat16* __restrict__ W1T,
    const float* __restrict__ b1, __nv_bfloat16* __restrict__ ffn)
{
    extern __shared__ char dynsm[];
    const uint32_t smBase = smem_u32(dynsm);
    gemm_core(hb, W1T, b1, b1, 1 << 30, nullptr, ffn,
              true, true, 1024, 256, blockIdx.y * 128, blockIdx.x * 128, smBase);
}

// ---------------- fused prep + weight transposes (single launch) ----------------
__device__ __forceinline__ void tr_tile(
    const float* __restrict__ W, __nv_bfloat16* __restrict__ WT,
    int K, int N, int kt, int nt, float (*tile)[33])
{
    const int k0 = kt * 32, n0 = nt * 32;
    const int tx = threadIdx.x & 31, ty = threadIdx.x >> 5;
#pragma unroll
    for (int r = 0; r < 4; r++)
        tile[ty + r * 8][tx] = W[(size_t)(k0 + ty + r * 8) * N + n0 + tx];
    __syncthreads();
#pragma unroll
    for (int r = 0; r < 4; r++)
        WT[(size_t)(n0 + ty + r * 8) * K + k0 + tx] = __float2bfloat16_rn(tile[tx][ty + r * 8]);
}

#define PREP_BLOCKS (M_ROWS * D_MODEL / 4 / 256)   // 10880

__global__ void __launch_bounds__(256) prep_all(
    const float* __restrict__ src, const float* __restrict__ pos,
    __nv_bfloat16* __restrict__ srcb, __nv_bfloat16* __restrict__ qsumb,
    const float* __restrict__ Wval, const float* __restrict__ Woff,
    const float* __restrict__ Wattn, const float* __restrict__ Wout,
    const float* __restrict__ W1, const float* __restrict__ W2,
    __nv_bfloat16* __restrict__ WvalT, __nv_bfloat16* __restrict__ WoaT,
    __nv_bfloat16* __restrict__ WoutT, __nv_bfloat16* __restrict__ W1T,
    __nv_bfloat16* __restrict__ W2T)
{
    __shared__ float tile[32][33];
    const int bx = blockIdx.x;
    if (bx < PREP_BLOCKS) {
        const int i = bx * 256 + threadIdx.x;
        float4 s = ((const float4*)src)[i];
        float4 p = ((const float4*)pos)[i];
        __nv_bfloat162* sb = (__nv_bfloat162*)srcb + i * 2;
        __nv_bfloat162* qb = (__nv_bfloat162*)qsumb + i * 2;
        sb[0] = __floats2bfloat162_rn(s.x, s.y);
        sb[1] = __floats2bfloat162_rn(s.z, s.w);
        qb[0] = __floats2bfloat162_rn(s.x + p.x, s.y + p.y);
        qb[1] = __floats2bfloat162_rn(s.z + p.z, s.w + p.w);
        return;
    }
    const int t = bx - PREP_BLOCKS;
    if (t < 64)       tr_tile(Wval, WvalT, 256, 256, t >> 3, t & 7, tile);
    else if (t < 128) { const int u = t - 64;  tr_tile(Woff, WoaT, 256, 256, u >> 3, u & 7, tile); }
    else if (t < 160) { const int u = t - 128; tr_tile(Wattn, WoaT + 256 * 256, 256, 128, u >> 2, u & 3, tile); }
    else if (t < 224) { const int u = t - 160; tr_tile(Wout, WoutT, 256, 256, u >> 3, u & 7, tile); }
    else if (t < 480) { const int u = t - 224; tr_tile(W1, W1T, 256, 1024, u >> 5, u & 31, tile); }
    else              { const int u = t - 480; tr_tile(W2, W2T, 1024, 256, u >> 3, u & 7, tile); }
}

// ---------------- sampler: warp per (bq, head-pair); bf16x2 channels ----------------
__global__ void __launch_bounds__(256) sample_bf(
    const __nv_bfloat16* __restrict__ value,
    const float* __restrict__ oa,
    const float* __restrict__ refp, __nv_bfloat16* __restrict__ samp)
{
    const int warp_id = (blockIdx.x * blockDim.x + threadIdx.x) >> 5;
    const int lane = threadIdx.x & 31;
    const int hh = warp_id & 3;
    const int bq = warp_id >> 2;
    const int b  = (bq >= LQ) ? 1 : 0;
    const int h  = hh * 2 + (lane >> 4);
    const int li = lane & 15;
    const int hsel = lane & 16;

    const float* al = oa + (size_t)bq * 384 + 256 + h * 16;
    const float logit = al[li];
    float mx = logit;
#pragma unroll
    for (int o = 8; o; o >>= 1) mx = fmaxf(mx, __shfl_xor_sync(0xffffffffu, mx, o));
    const float e = __expf(logit - mx);
    float se = e;
#pragma unroll
    for (int o = 8; o; o >>= 1) se += __shfl_xor_sync(0xffffffffu, se, o);
    const float inv_se = 1.f / se;

    int cip; uint32_t wpk01, wpk23;
    {
        const int lvl = li >> 2;
        const int Ww = 128 >> lvl;
        const float fW = (float)Ww;
        const float invW = 1.f / fW;
        const int st = c_ST[lvl];

        const float* op = oa + (size_t)bq * 384 + h * 32;
        const float ox = op[li * 2 + 0];
        const float oy = op[li * 2 + 1];
        const float* rp = refp + (size_t)bq * 8;
        const float rx = rp[lvl * 2 + 0];
        const float ry = rp[lvl * 2 + 1];

        const float x = (rx + ox * invW) * fW - 0.5f;
        const float y = (ry + oy * invW) * fW - 0.5f;
        const float x0f = floorf(x), y0f = floorf(y);
        const int x0 = (int)x0f, y0 = (int)y0f;
        const float wx1 = x - x0f, wy1 = y - y0f;
        const float wx0 = 1.f - wx1, wy0 = 1.f - wy1;

        const float w = e * inv_se;
        const float vx0 = (x0 >= 0 && x0 < Ww) ? 1.f : 0.f;
        const float vx1 = (x0 + 1 >= 0 && x0 + 1 < Ww) ? 1.f : 0.f;
        const float vy0 = (y0 >= 0 && y0 < Ww) ? 1.f : 0.f;
        const float vy1 = (y0 + 1 >= 0 && y0 + 1 < Ww) ? 1.f : 0.f;

        const float cw0 = w * (wx0 * wy0) * (vx0 * vy0);
        const float cw1 = w * (wx1 * wy0) * (vx1 * vy0);
        const float cw2 = w * (wx0 * wy1) * (vx0 * vy1);
        const float cw3 = w * (wx1 * wy1) * (vx1 * vy1);

        const int xc0 = min(max(x0, 0), Ww - 1);
        const int xc1 = min(max(x0 + 1, 0), Ww - 1);
        const int yc0 = min(max(y0, 0), Ww - 1);
        const int yc1 = min(max(y0 + 1, 0), Ww - 1);
        cip = ((st + yc0 * Ww + xc0) << 2) | ((yc1 - yc0) << 1) | (xc1 - xc0);

        __half2 ha = __floats2half2_rn(cw0, cw1);
        __half2 hb2 = __floats2half2_rn(cw2, cw3);
        wpk01 = *(uint32_t*)&ha;
        wpk23 = *(uint32_t*)&hb2;
    }

    const __nv_bfloat162* v2 = (const __nv_bfloat162*)value
        + (size_t)b * LQ * 128 + h * 16 + li;
    float ax0 = 0.f, ay0 = 0.f, ax1 = 0.f, ay1 = 0.f;
#pragma unroll
    for (int p = 0; p < 16; p++) {
        const int src = hsel | p;
        const int pk = __shfl_sync(0xffffffffu, cip, src);
        const uint32_t wa = __shfl_sync(0xffffffffu, wpk01, src);
        const uint32_t wb = __shfl_sync(0xffffffffu, wpk23, src);
        const int tok = pk >> 2;
        const int dx  = pk & 1;
        const int dyW = ((pk >> 1) & 1) * (128 >> (p >> 2));

        const __nv_bfloat162 r00 = __ldg(v2 + (size_t)tok * 128);
        const __nv_bfloat162 r10 = __ldg(v2 + (size_t)(tok + dx) * 128);
        const __nv_bfloat162 r01 = __ldg(v2 + (size_t)(tok + dyW) * 128);
        const __nv_bfloat162 r11 = __ldg(v2 + (size_t)(tok + dyW + dx) * 128);

        const float2 w01 = __half22float2(*(const __half2*)&wa);
        const float2 w23 = __half22float2(*(const __half2*)&wb);
        float2 f;
        f = __bfloat1622float2(r00); ax0 += w01.x * f.x; ay0 += w01.x * f.y;
        f = __bfloat1622float2(r10); ax1 += w01.y * f.x; ay1 += w01.y * f.y;
        f = __bfloat1622float2(r01); ax0 += w23.x * f.x; ay0 += w23.x * f.y;
        f = __bfloat1622float2(r11); ax1 += w23.y * f.x; ay1 += w23.y * f.y;
    }
    ((__nv_bfloat162*)(samp + (size_t)bq * 256 + h * 32))[li] =
        __floats2bfloat162_rn(ax0 + ax1, ay0 + ay1);
}

// ---------------- layernorm: one warp per row, float4 ----------------
template <bool WRBF>
__global__ void __launch_bounds__(256) ln4_kernel(
    const float* __restrict__ in, const float* __restrict__ g,
    const float* __restrict__ b, float* __restrict__ out, __nv_bfloat16* __restrict__ outbf)
{
    const int lane = threadIdx.x & 31;
    const size_t row = blockIdx.x * 8 + (threadIdx.x >> 5);
    const float4* in4 = (const float4*)(in + row * 256);
    const float4 A = in4[lane * 2], B4 = in4[lane * 2 + 1];

    float s = A.x + A.y + A.z + A.w + B4.x + B4.y + B4.z + B4.w;
#pragma unroll
    for (int o = 16; o; o >>= 1) s += __shfl_xor_sync(0xffffffffu, s, o);
    const float mu = s * (1.f / 256.f);

    float4 dA, dB;
    dA.x = A.x - mu; dA.y = A.y - mu; dA.z = A.z - mu; dA.w = A.w - mu;
    dB.x = B4.x - mu; dB.y = B4.y - mu; dB.z = B4.z - mu; dB.w = B4.w - mu;
    float v = dA.x*dA.x + dA.y*dA.y + dA.z*dA.z + dA.w*dA.w
            + dB.x*dB.x + dB.y*dB.y + dB.z*dB.z + dB.w*dB.w;
#pragma unroll
    for (int o = 16; o; o >>= 1) v += __shfl_xor_sync(0xffffffffu, v, o);
    const float rstd = rsqrtf(v * (1.f / 256.f) + 1e-5f);

    const float4 gA = ((const float4*)g)[lane * 2], gB = ((const float4*)g)[lane * 2 + 1];
    const float4 bA = ((const float4*)b)[lane * 2], bB = ((const float4*)b)[lane * 2 + 1];
    float4 yA, yB;
    yA.x = dA.x * rstd * gA.x + bA.x; yA.y = dA.y * rstd * gA.y + bA.y;
    yA.z = dA.z * rstd * gA.z + bA.z; yA.w = dA.w * rstd * gA.w + bA.w;
    yB.x = dB.x * rstd * gB.x + bB.x; yB.y = dB.y * rstd * gB.y + bB.y;
    yB.z = dB.z * rstd * gB.z + bB.z; yB.w = dB.w * rstd * gB.w + bB.w;

    float4* o4 = (float4*)(out + row * 256);
    o4[lane * 2] = yA; o4[lane * 2 + 1] = yB;
    if (WRBF) {
        __nv_bfloat162* r2 = (__nv_bfloat162*)(outbf + row * 256) + lane * 4;
        r2[0] = __floats2bfloat162_rn(yA.x, yA.y);
        r2[1] = __floats2bfloat162_rn(yA.z, yA.w);
        r2[2] = __floats2bfloat162_rn(yB.x, yB.y);
        r2[3] = __floats2bfloat162_rn(yB.z, yB.w);
    }
}

// ---------------- launch ----------------
extern "C" void kernel_launch(void* const* d_in, const int* in_sizes, int n_in,
                              void* d_out, int out_size)
{
    const float* src    = (const float*)d_in[0];
    const float* pos    = (const float*)d_in[1];
    const float* refp   = (const float*)d_in[2];
    const float* W_off  = (const float*)d_in[3];
    const float* b_off  = (const float*)d_in[4];
    const float* W_attn = (const float*)d_in[5];
    const float* b_attn = (const float*)d_in[6];
    const float* W_val  = (const float*)d_in[7];
    const float* b_val  = (const float*)d_in[8];
    const float* W_out  = (const float*)d_in[9];
    const float* b_out  = (const float*)d_in[10];
    const float* ln1_g  = (const float*)d_in[11];
    const float* ln1_b  = (const float*)d_in[12];
    const float* W1     = (const float*)d_in[13];
    const float* b1     = (const float*)d_in[14];
    const float* W2     = (const float*)d_in[15];
    const float* b2     = (const float*)d_in[16];
    const float* ln2_g  = (const float*)d_in[17];
    const float* ln2_b  = (const float*)d_in[18];
    float* out = (float*)d_out;

    __nv_bfloat16 *p_srcb, *p_qsumb, *p_value, *p_samp, *p_hb, *p_ffn;
    __nv_bfloat16 *p_WvalT, *p_WoaT, *p_WoutT, *p_W1T, *p_W2T;
    float *p_oa, *p_h, *p_t2;
    cudaGetSymbolAddress((void**)&p_srcb,  g_srcb);
    cudaGetSymbolAddress((void**)&p_qsumb, g_qsumb);
    cudaGetSymbolAddress((void**)&p_value, g_value);
    cudaGetSymbolAddress((void**)&p_oa,    g_oa);
    cudaGetSymbolAddress((void**)&p_samp,  g_samp);
    cudaGetSymbolAddress((void**)&p_h,     g_h);
    cudaGetSymbolAddress((void**)&p_hb,    g_hb);
    cudaGetSymbolAddress((void**)&p_ffn,   g_ffn);
    cudaGetSymbolAddress((void**)&p_t2,    g_t2);
    cudaGetSymbolAddress((void**)&p_WvalT, g_WvalT);
    cudaGetSymbolAddress((void**)&p_WoaT,  g_WoaT);
    cudaGetSymbolAddress((void**)&p_WoutT, g_WoutT);
    cudaGetSymbolAddress((void**)&p_W1T,   g_W1T);
    cudaGetSymbolAddress((void**)&p_W2T,   g_W2T);

    float* p_t1 = p_oa;   // reuse: oa dead after sampling, t1 written afterward

    const int SMEM_GEMM = 3 * 32768;   // 96 KB
    cudaFuncSetAttribute(gemm_proj, cudaFuncAttributeMaxDynamicSharedMemorySize, SMEM_GEMM);
    cudaFuncSetAttribute(gemm_res,  cudaFuncAttributeMaxDynamicSharedMemorySize, SMEM_GEMM);
    cudaFuncSetAttribute(gemm_ffn,  cudaFuncAttributeMaxDynamicSharedMemorySize, SMEM_GEMM);

    const int M = M_ROWS;
    const int MT = M / 128;   // 340

    // 0: prep + all weight transposes
    prep_all<<<PREP_BLOCKS + 736, 256>>>(src, pos, p_srcb, p_qsumb,
        W_val, W_off, W_attn, W_out, W1, W2,
        p_WvalT, p_WoaT, p_WoutT, p_W1T, p_W2T);
    // 1: value + oa projections (merged)
    gemm_proj<<<dim3(5, MT), 256, SMEM_GEMM>>>(
        p_srcb, p_qsumb, p_WvalT, p_WoaT, b_val, b_off, b_attn, p_value, p_oa);
    // 2: deformable sampling
    sample_bf<<<M / 2, 256>>>(p_value, p_oa, refp, p_samp);
    // 3: t1 = samp @ W_out + b_out + src   (t1 aliases oa)
    gemm_res<<<dim3(2, MT), 256, SMEM_GEMM>>>(p_samp, p_WoutT, b_out, src, p_t1, 256);
    // 4: h = LN1(t1) (+ bf16 copy hb)
    ln4_kernel<true><<<M / 8, 256>>>(p_t1, ln1_g, ln1_b, p_h, p_hb);
    // 5: ffn = relu(h @ W1 + b1)  (bf16)
    gemm_ffn<<<dim3(8, MT), 256, SMEM_GEMM>>>(p_hb, p_W1T, b1, p_ffn);
    // 6: t2 = ffn @ W2 + b2 + h
    gemm_res<<<dim3(2, MT), 256, SMEM_GEMM>>>(p_ffn, p_W2T, b2, p_h, p_t2, 1024);
    // 7: out = LN2(t2)
    ln4_kernel<false><<<M / 8, 256>>>(p_t2, ln2_g, ln2_b, out, nullptr);
}

// round 14
// speedup vs baseline: 1.1072x; 1.1072x over previous
#include <cuda_runtime.h>
#include <cuda_bf16.h>
#include <cuda_fp16.h>
#include <math.h>
#include <stdint.h>

// ---------------- problem constants ----------------
#define D_MODEL 256
#define D_FFN   1024
#define LQ      21760
#define BATCH   2
#define M_ROWS  (BATCH * LQ)   // 43520

__device__ __constant__ int c_ST[4] = {0, 16384, 20480, 21504};

// ---------------- scratch ----------------
__device__ __nv_bfloat16 g_srcb [(size_t)M_ROWS * D_MODEL];
__device__ __nv_bfloat16 g_qsumb[(size_t)M_ROWS * D_MODEL];
__device__ __nv_bfloat16 g_value[(size_t)M_ROWS * D_MODEL];
__device__ float g_oa   [(size_t)M_ROWS * 384];   // oa; reused as t1 after sampling
__device__ __nv_bfloat16 g_samp [(size_t)M_ROWS * D_MODEL];
__device__ float g_h    [(size_t)M_ROWS * D_MODEL];
__device__ __nv_bfloat16 g_hb   [(size_t)M_ROWS * D_MODEL];
__device__ __nv_bfloat16 g_ffn  [(size_t)M_ROWS * D_FFN];
__device__ float g_t2   [(size_t)M_ROWS * D_MODEL];
__device__ __nv_bfloat16 g_WvalT [256 * 256];
__device__ __nv_bfloat16 g_WoaT  [384 * 256];
__device__ __nv_bfloat16 g_WoutT [256 * 256];
__device__ __nv_bfloat16 g_W1T   [1024 * 256];
__device__ __nv_bfloat16 g_W2T   [256 * 1024];

// ---------------- helpers ----------------
__device__ __forceinline__ uint32_t smem_u32(const void* p) {
    uint32_t a;
    asm("{ .reg .u64 t; cvta.to.shared.u64 t, %1; cvt.u32.u64 %0, t; }" : "=r"(a) : "l"(p));
    return a;
}
__device__ __forceinline__ void cpasync16(uint32_t dst, const void* src) {
    asm volatile("cp.async.cg.shared.global [%0], [%1], 16;" :: "r"(dst), "l"(src));
}
__device__ __forceinline__ void ldsm_x4(uint32_t& r0, uint32_t& r1, uint32_t& r2, uint32_t& r3, uint32_t addr) {
    asm volatile("ldmatrix.sync.aligned.m8n8.x4.shared.b16 {%0,%1,%2,%3}, [%4];"
        : "=r"(r0), "=r"(r1), "=r"(r2), "=r"(r3) : "r"(addr));
}
__device__ __forceinline__ void mma_bf16(float* d, const uint32_t* a, const uint32_t* b) {
    asm volatile("mma.sync.aligned.m16n8k16.row.col.f32.bf16.bf16.f32 "
        "{%0,%1,%2,%3}, {%4,%5,%6,%7}, {%8,%9}, {%0,%1,%2,%3};"
        : "+f"(d[0]), "+f"(d[1]), "+f"(d[2]), "+f"(d[3])
        : "r"(a[0]), "r"(a[1]), "r"(a[2]), "r"(a[3]), "r"(b[0]), "r"(b[1]));
}

// ---------------- tensor-core bf16 GEMM: BK=64, 3-stage cp.async (R10 proven) -------
template <bool RESF, bool RELUF, bool BF16OUT>
__global__ void __launch_bounds__(256, 2) gemm_mma(
    const __nv_bfloat16* __restrict__ A, const __nv_bfloat16* __restrict__ WT,
    const float* __restrict__ bias, const float* __restrict__ bias2, int nsplit,
    const float* __restrict__ res, void* __restrict__ Cout, int N, int K)
{
    extern __shared__ char dynsm[];
    const uint32_t smBase = smem_u32(dynsm);

    const int tid = threadIdx.x;
    const int lane = tid & 31;
    const int wid = tid >> 5;
    const int wm = wid & 1;
    const int wn = wid >> 1;
    const int bm = blockIdx.y * 128;
    const int bn = blockIdx.x * 128;

    const __nv_bfloat16* aG[4]; const __nv_bfloat16* bG[4];
    uint32_t sOff[4];
#pragma unroll
    for (int i = 0; i < 4; i++) {
        const int id = tid + i * 256;
        const int row = id >> 3, ck = id & 7;
        aG[i] = A  + (size_t)(bm + row) * K + ck * 8;
        bG[i] = WT + (size_t)(bn + row) * K + ck * 8;
        sOff[i] = row * 128 + ((ck ^ (row & 7)) * 16);
    }

    const int aRow = wm * 64 + (lane & 15);
    const int aCkH = lane >> 4;
    const int bRow = wn * 32 + ((lane >> 4) & 1) * 8 + (lane & 7);
    const int bCkH = (lane >> 3) & 1;

    float acc[4][4][4];
#pragma unroll
    for (int i = 0; i < 4; i++)
#pragma unroll
        for (int j = 0; j < 4; j++)
#pragma unroll
            for (int k = 0; k < 4; k++) acc[i][j][k] = 0.f;

    const int Cs = K >> 6;

#pragma unroll
    for (int i = 0; i < 4; i++) {
        cpasync16(smBase + sOff[i], aG[i]);
        cpasync16(smBase + 16384 + sOff[i], bG[i]);
    }
    asm volatile("cp.async.commit_group;" ::: "memory");
#pragma unroll
    for (int i = 0; i < 4; i++) {
        cpasync16(smBase + 32768 + sOff[i], aG[i] + 64);
        cpasync16(smBase + 32768 + 16384 + sOff[i], bG[i] + 64);
    }
    asm volatile("cp.async.commit_group;" ::: "memory");

    int st = 0, ldst = 2;
    for (int c = 0; c < Cs; ++c) {
        if (c == Cs - 1) asm volatile("cp.async.wait_group 0;" ::: "memory");
        else             asm volatile("cp.async.wait_group 1;" ::: "memory");
        __syncthreads();

        const uint32_t sA = smBase + (uint32_t)st * 32768;
        const uint32_t sB = sA + 16384;

#pragma unroll
        for (int ks = 0; ks < 4; ks++) {
            uint32_t af[4][4];
            uint32_t bfr[2][4];
#pragma unroll
            for (int mt = 0; mt < 4; mt++) {
                const int row = aRow + mt * 16;
                const int ck = ks * 2 + aCkH;
                ldsm_x4(af[mt][0], af[mt][1], af[mt][2], af[mt][3],
                        sA + row * 128 + ((ck ^ (row & 7)) * 16));
            }
#pragma unroll
            for (int np = 0; np < 2; np++) {
                const int row = bRow + np * 16;
                const int ck = ks * 2 + bCkH;
                ldsm_x4(bfr[np][0], bfr[np][1], bfr[np][2], bfr[np][3],
                        sB + row * 128 + ((ck ^ (row & 7)) * 16));
            }
#pragma unroll
            for (int mt = 0; mt < 4; mt++)
#pragma unroll
                for (int nt = 0; nt < 4; nt++)
                    mma_bf16(acc[mt][nt], af[mt], &bfr[nt >> 1][(nt & 1) * 2]);
        }

        if (c + 2 < Cs) {
            const int k0 = (c + 2) << 6;
            const uint32_t dA = smBase + (uint32_t)ldst * 32768;
#pragma unroll
            for (int i = 0; i < 4; i++) {
                cpasync16(dA + sOff[i], aG[i] + k0);
                cpasync16(dA + 16384 + sOff[i], bG[i] + k0);
            }
            asm volatile("cp.async.commit_group;" ::: "memory");
        }
        st = (st == 2) ? 0 : st + 1;
        ldst = (ldst == 2) ? 0 : ldst + 1;
    }

    const int r0base = bm + wm * 64 + (lane >> 2);
    const int cbase  = bn + wn * 32 + (lane & 3) * 2;
#pragma unroll
    for (int mt = 0; mt < 4; mt++) {
#pragma unroll
        for (int nt = 0; nt < 4; nt++) {
            const int col = cbase + nt * 8;
            const float bx = (col < nsplit) ? bias[col] : bias2[col - nsplit];
            const float by = (col + 1 < nsplit) ? bias[col + 1] : bias2[col + 1 - nsplit];
#pragma unroll
            for (int half = 0; half < 2; half++) {
                const int row = r0base + mt * 16 + half * 8;
                float vx = acc[mt][nt][half * 2 + 0] + bx;
                float vy = acc[mt][nt][half * 2 + 1] + by;
                if (RESF) {
                    const float* rp = res + (size_t)row * N + col;
                    vx += rp[0]; vy += rp[1];
                }
                if (RELUF) { vx = fmaxf(vx, 0.f); vy = fmaxf(vy, 0.f); }
                if (BF16OUT) {
                    __nv_bfloat162 bb = __floats2bfloat162_rn(vx, vy);
                    *(__nv_bfloat162*)((__nv_bfloat16*)Cout + (size_t)row * N + col) = bb;
                } else {
                    *(float2*)((float*)Cout + (size_t)row * N + col) = make_float2(vx, vy);
                }
            }
        }
    }
}

// ---------------- fused prep + weight transposes (single launch) ----------------
__device__ __forceinline__ void tr_tile(
    const float* __restrict__ W, __nv_bfloat16* __restrict__ WT,
    int K, int N, int kt, int nt, float (*tile)[33])
{
    const int k0 = kt * 32, n0 = nt * 32;
    const int tx = threadIdx.x & 31, ty = threadIdx.x >> 5;
#pragma unroll
    for (int r = 0; r < 4; r++)
        tile[ty + r * 8][tx] = W[(size_t)(k0 + ty + r * 8) * N + n0 + tx];
    __syncthreads();
#pragma unroll
    for (int r = 0; r < 4; r++)
        WT[(size_t)(n0 + ty + r * 8) * K + k0 + tx] = __float2bfloat16_rn(tile[tx][ty + r * 8]);
}

#define PREP_BLOCKS (M_ROWS * D_MODEL / 4 / 256)   // 10880

__global__ void __launch_bounds__(256) prep_all(
    const float* __restrict__ src, const float* __restrict__ pos,
    __nv_bfloat16* __restrict__ srcb, __nv_bfloat16* __restrict__ qsumb,
    const float* __restrict__ Wval, const float* __restrict__ Woff,
    const float* __restrict__ Wattn, const float* __restrict__ Wout,
    const float* __restrict__ W1, const float* __restrict__ W2,
    __nv_bfloat16* __restrict__ WvalT, __nv_bfloat16* __restrict__ WoaT,
    __nv_bfloat16* __restrict__ WoutT, __nv_bfloat16* __restrict__ W1T,
    __nv_bfloat16* __restrict__ W2T)
{
    __shared__ float tile[32][33];
    const int bx = blockIdx.x;
    if (bx < PREP_BLOCKS) {
        const int i = bx * 256 + threadIdx.x;
        float4 s = ((const float4*)src)[i];
        float4 p = ((const float4*)pos)[i];
        __nv_bfloat162* sb = (__nv_bfloat162*)srcb + i * 2;
        __nv_bfloat162* qb = (__nv_bfloat162*)qsumb + i * 2;
        sb[0] = __floats2bfloat162_rn(s.x, s.y);
        sb[1] = __floats2bfloat162_rn(s.z, s.w);
        qb[0] = __floats2bfloat162_rn(s.x + p.x, s.y + p.y);
        qb[1] = __floats2bfloat162_rn(s.z + p.z, s.w + p.w);
        return;
    }
    const int t = bx - PREP_BLOCKS;
    if (t < 64)       tr_tile(Wval, WvalT, 256, 256, t >> 3, t & 7, tile);
    else if (t < 128) { const int u = t - 64;  tr_tile(Woff, WoaT, 256, 256, u >> 3, u & 7, tile); }
    else if (t < 160) { const int u = t - 128; tr_tile(Wattn, WoaT + 256 * 256, 256, 128, u >> 2, u & 3, tile); }
    else if (t < 224) { const int u = t - 160; tr_tile(Wout, WoutT, 256, 256, u >> 3, u & 7, tile); }
    else if (t < 480) { const int u = t - 224; tr_tile(W1, W1T, 256, 1024, u >> 5, u & 31, tile); }
    else              { const int u = t - 480; tr_tile(W2, W2T, 1024, 256, u >> 3, u & 7, tile); }
}

// ---------------- sampler: warp per (bq, head-pair); bf16x2 channels (R10) ----------
__global__ void __launch_bounds__(256) sample_bf(
    const __nv_bfloat16* __restrict__ value,
    const float* __restrict__ oa,
    const float* __restrict__ refp, __nv_bfloat16* __restrict__ samp)
{
    const int warp_id = (blockIdx.x * blockDim.x + threadIdx.x) >> 5;
    const int lane = threadIdx.x & 31;
    const int hh = warp_id & 3;
    const int bq = warp_id >> 2;
    const int b  = (bq >= LQ) ? 1 : 0;
    const int h  = hh * 2 + (lane >> 4);
    const int li = lane & 15;
    const int hsel = lane & 16;

    const float* al = oa + (size_t)bq * 384 + 256 + h * 16;
    const float logit = al[li];
    float mx = logit;
#pragma unroll
    for (int o = 8; o; o >>= 1) mx = fmaxf(mx, __shfl_xor_sync(0xffffffffu, mx, o));
    const float e = __expf(logit - mx);
    float se = e;
#pragma unroll
    for (int o = 8; o; o >>= 1) se += __shfl_xor_sync(0xffffffffu, se, o);
    const float inv_se = 1.f / se;

    int cip; uint32_t wpk01, wpk23;
    {
        const int lvl = li >> 2;
        const int Ww = 128 >> lvl;
        const float fW = (float)Ww;
        const float invW = 1.f / fW;
        const int st = c_ST[lvl];

        const float* op = oa + (size_t)bq * 384 + h * 32;
        const float ox = op[li * 2 + 0];
        const float oy = op[li * 2 + 1];
        const float* rp = refp + (size_t)bq * 8;
        const float rx = rp[lvl * 2 + 0];
        const float ry = rp[lvl * 2 + 1];

        const float x = (rx + ox * invW) * fW - 0.5f;
        const float y = (ry + oy * invW) * fW - 0.5f;
        const float x0f = floorf(x), y0f = floorf(y);
        const int x0 = (int)x0f, y0 = (int)y0f;
        const float wx1 = x - x0f, wy1 = y - y0f;
        const float wx0 = 1.f - wx1, wy0 = 1.f - wy1;

        const float w = e * inv_se;
        const float vx0 = (x0 >= 0 && x0 < Ww) ? 1.f : 0.f;
        const float vx1 = (x0 + 1 >= 0 && x0 + 1 < Ww) ? 1.f : 0.f;
        const float vy0 = (y0 >= 0 && y0 < Ww) ? 1.f : 0.f;
        const float vy1 = (y0 + 1 >= 0 && y0 + 1 < Ww) ? 1.f : 0.f;

        const float cw0 = w * (wx0 * wy0) * (vx0 * vy0);
        const float cw1 = w * (wx1 * wy0) * (vx1 * vy0);
        const float cw2 = w * (wx0 * wy1) * (vx0 * vy1);
        const float cw3 = w * (wx1 * wy1) * (vx1 * vy1);

        const int xc0 = min(max(x0, 0), Ww - 1);
        const int xc1 = min(max(x0 + 1, 0), Ww - 1);
        const int yc0 = min(max(y0, 0), Ww - 1);
        const int yc1 = min(max(y0 + 1, 0), Ww - 1);
        cip = ((st + yc0 * Ww + xc0) << 2) | ((yc1 - yc0) << 1) | (xc1 - xc0);

        __half2 ha = __floats2half2_rn(cw0, cw1);
        __half2 hb2 = __floats2half2_rn(cw2, cw3);
        wpk01 = *(uint32_t*)&ha;
        wpk23 = *(uint32_t*)&hb2;
    }

    const __nv_bfloat162* v2 = (const __nv_bfloat162*)value
        + (size_t)b * LQ * 128 + h * 16 + li;
    float ax0 = 0.f, ay0 = 0.f, ax1 = 0.f, ay1 = 0.f;
#pragma unroll
    for (int p = 0; p < 16; p++) {
        const int src = hsel | p;
        const int pk = __shfl_sync(0xffffffffu, cip, src);
        const uint32_t wa = __shfl_sync(0xffffffffu, wpk01, src);
        const uint32_t wb = __shfl_sync(0xffffffffu, wpk23, src);
        const int tok = pk >> 2;
        const int dx  = pk & 1;
        const int dyW = ((pk >> 1) & 1) * (128 >> (p >> 2));

        const __nv_bfloat162 r00 = __ldg(v2 + (size_t)tok * 128);
        const __nv_bfloat162 r10 = __ldg(v2 + (size_t)(tok + dx) * 128);
        const __nv_bfloat162 r01 = __ldg(v2 + (size_t)(tok + dyW) * 128);
        const __nv_bfloat162 r11 = __ldg(v2 + (size_t)(tok + dyW + dx) * 128);

        const float2 w01 = __half22float2(*(const __half2*)&wa);
        const float2 w23 = __half22float2(*(const __half2*)&wb);
        float2 f;
        f = __bfloat1622float2(r00); ax0 += w01.x * f.x; ay0 += w01.x * f.y;
        f = __bfloat1622float2(r10); ax1 += w01.y * f.x; ay1 += w01.y * f.y;
        f = __bfloat1622float2(r01); ax0 += w23.x * f.x; ay0 += w23.x * f.y;
        f = __bfloat1622float2(r11); ax1 += w23.y * f.x; ay1 += w23.y * f.y;
    }
    ((__nv_bfloat162*)(samp + (size_t)bq * 256 + h * 32))[li] =
        __floats2bfloat162_rn(ax0 + ax1, ay0 + ay1);
}

// ---------------- layernorm: one warp per row, float4 (R10) ----------------
template <bool WRBF>
__global__ void __launch_bounds__(256) ln4_kernel(
    const float* __restrict__ in, const float* __restrict__ g,
    const float* __restrict__ b, float* __restrict__ out, __nv_bfloat16* __restrict__ outbf)
{
    const int lane = threadIdx.x & 31;
    const size_t row = blockIdx.x * 8 + (threadIdx.x >> 5);
    const float4* in4 = (const float4*)(in + row * 256);
    const float4 A = in4[lane * 2], B4 = in4[lane * 2 + 1];

    float s = A.x + A.y + A.z + A.w + B4.x + B4.y + B4.z + B4.w;
#pragma unroll
    for (int o = 16; o; o >>= 1) s += __shfl_xor_sync(0xffffffffu, s, o);
    const float mu = s * (1.f / 256.f);

    float4 dA, dB;
    dA.x = A.x - mu; dA.y = A.y - mu; dA.z = A.z - mu; dA.w = A.w - mu;
    dB.x = B4.x - mu; dB.y = B4.y - mu; dB.z = B4.z - mu; dB.w = B4.w - mu;
    float v = dA.x*dA.x + dA.y*dA.y + dA.z*dA.z + dA.w*dA.w
            + dB.x*dB.x + dB.y*dB.y + dB.z*dB.z + dB.w*dB.w;
#pragma unroll
    for (int o = 16; o; o >>= 1) v += __shfl_xor_sync(0xffffffffu, v, o);
    const float rstd = rsqrtf(v * (1.f / 256.f) + 1e-5f);

    const float4 gA = ((const float4*)g)[lane * 2], gB = ((const float4*)g)[lane * 2 + 1];
    const float4 bA = ((const float4*)b)[lane * 2], bB = ((const float4*)b)[lane * 2 + 1];
    float4 yA, yB;
    yA.x = dA.x * rstd * gA.x + bA.x; yA.y = dA.y * rstd * gA.y + bA.y;
    yA.z = dA.z * rstd * gA.z + bA.z; yA.w = dA.w * rstd * gA.w + bA.w;
    yB.x = dB.x * rstd * gB.x + bB.x; yB.y = dB.y * rstd * gB.y + bB.y;
    yB.z = dB.z * rstd * gB.z + bB.z; yB.w = dB.w * rstd * gB.w + bB.w;

    float4* o4 = (float4*)(out + row * 256);
    o4[lane * 2] = yA; o4[lane * 2 + 1] = yB;
    if (WRBF) {
        __nv_bfloat162* r2 = (__nv_bfloat162*)(outbf + row * 256) + lane * 4;
        r2[0] = __floats2bfloat162_rn(yA.x, yA.y);
        r2[1] = __floats2bfloat162_rn(yA.z, yA.w);
        r2[2] = __floats2bfloat162_rn(yB.x, yB.y);
        r2[3] = __floats2bfloat162_rn(yB.z, yB.w);
    }
}

// ---------------- launch ----------------
extern "C" void kernel_launch(void* const* d_in, const int* in_sizes, int n_in,
                              void* d_out, int out_size)
{
    const float* src    = (const float*)d_in[0];
    const float* pos    = (const float*)d_in[1];
    const float* refp   = (const float*)d_in[2];
    const float* W_off  = (const float*)d_in[3];
    const float* b_off  = (const float*)d_in[4];
    const float* W_attn = (const float*)d_in[5];
    const float* b_attn = (const float*)d_in[6];
    const float* W_val  = (const float*)d_in[7];
    const float* b_val  = (const float*)d_in[8];
    const float* W_out  = (const float*)d_in[9];
    const float* b_out  = (const float*)d_in[10];
    const float* ln1_g  = (const float*)d_in[11];
    const float* ln1_b  = (const float*)d_in[12];
    const float* W1     = (const float*)d_in[13];
    const float* b1     = (const float*)d_in[14];
    const float* W2     = (const float*)d_in[15];
    const float* b2     = (const float*)d_in[16];
    const float* ln2_g  = (const float*)d_in[17];
    const float* ln2_b  = (const float*)d_in[18];
    float* out = (float*)d_out;

    __nv_bfloat16 *p_srcb, *p_qsumb, *p_value, *p_samp, *p_hb, *p_ffn;
    __nv_bfloat16 *p_WvalT, *p_WoaT, *p_WoutT, *p_W1T, *p_W2T;
    float *p_oa, *p_h, *p_t2;
    cudaGetSymbolAddress((void**)&p_srcb,  g_srcb);
    cudaGetSymbolAddress((void**)&p_qsumb, g_qsumb);
    cudaGetSymbolAddress((void**)&p_value, g_value);
    cudaGetSymbolAddress((void**)&p_oa,    g_oa);
    cudaGetSymbolAddress((void**)&p_samp,  g_samp);
    cudaGetSymbolAddress((void**)&p_h,     g_h);
    cudaGetSymbolAddress((void**)&p_hb,    g_hb);
    cudaGetSymbolAddress((void**)&p_ffn,   g_ffn);
    cudaGetSymbolAddress((void**)&p_t2,    g_t2);
    cudaGetSymbolAddress((void**)&p_WvalT, g_WvalT);
    cudaGetSymbolAddress((void**)&p_WoaT,  g_WoaT);
    cudaGetSymbolAddress((void**)&p_WoutT, g_WoutT);
    cudaGetSymbolAddress((void**)&p_W1T,   g_W1T);
    cudaGetSymbolAddress((void**)&p_W2T,   g_W2T);

    float* p_t1 = p_oa;   // reuse: oa dead after sampling

    const int SMEM_BYTES = 3 * 32768;  // 96 KB
    cudaFuncSetAttribute(gemm_mma<false, false, true >, cudaFuncAttributeMaxDynamicSharedMemorySize, SMEM_BYTES);
    cudaFuncSetAttribute(gemm_mma<false, false, false>, cudaFuncAttributeMaxDynamicSharedMemorySize, SMEM_BYTES);
    cudaFuncSetAttribute(gemm_mma<true,  false, false>, cudaFuncAttributeMaxDynamicSharedMemorySize, SMEM_BYTES);
    cudaFuncSetAttribute(gemm_mma<false, true,  true >, cudaFuncAttributeMaxDynamicSharedMemorySize, SMEM_BYTES);

    const int M = M_ROWS;
    const int MT = M / 128;  // 340
    const int BIG = 1 << 30;

    // 0: prep + all weight transposes (fused)
    prep_all<<<PREP_BLOCKS + 736, 256>>>(src, pos, p_srcb, p_qsumb,
        W_val, W_off, W_attn, W_out, W1, W2,
        p_WvalT, p_WoaT, p_WoutT, p_W1T, p_W2T);
    // 1: value (bf16) = src @ W_val + b_val
    gemm_mma<false, false, true><<<dim3(2, MT), 256, SMEM_BYTES>>>(
        p_srcb, p_WvalT, b_val, b_val, BIG, nullptr, p_value, 256, 256);
    // 2: oa (fp32) = (src+pos) @ [W_off|W_attn] + [b_off|b_attn]
    gemm_mma<false, false, false><<<dim3(3, MT), 256, SMEM_BYTES>>>(
        p_qsumb, p_WoaT, b_off, b_attn, 256, nullptr, p_oa, 384, 256);
    // 3: sampling
    sample_bf<<<M / 2, 256>>>(p_value, p_oa, refp, p_samp);
    // 4: t1 = samp @ W_out + b_out + src  (t1 aliases oa)
    gemm_mma<true, false, false><<<dim3(2, MT), 256, SMEM_BYTES>>>(
        p_samp, p_WoutT, b_out, b_out, BIG, src, p_t1, 256, 256);
    // 5: h = LN1(t1) (+ bf16 copy hb)   <- ncu -s 5 -c 1
    ln4_kernel<true><<<M / 8, 256>>>(p_t1, ln1_g, ln1_b, p_h, p_hb);
    // 6: ffn = relu(h @ W1 + b1)  (bf16)
    gemm_mma<false, true, true><<<dim3(8, MT), 256, SMEM_BYTES>>>(
        p_hb, p_W1T, b1, b1, BIG, nullptr, p_ffn, 1024, 256);
    // 7: t2 = ffn @ W2 + b2 + h
    gemm_mma<true, false, false><<<dim3(2, MT), 256, SMEM_BYTES>>>(
        p_ffn, p_W2T, b2, b2, BIG, p_h, p_t2, 256, 1024);
    // 8: out = LN2(t2)
    ln4_kernel<false><<<M / 8, 256>>>(p_t2, ln2_g, ln2_b, out, nullptr);
}

// round 16
// speedup vs baseline: 1.2126x; 1.0952x over previous
#include <cuda_runtime.h>
#include <cuda_bf16.h>
#include <cuda_fp16.h>
#include <math.h>
#include <stdint.h>

// ---------------- problem constants ----------------
#define D_MODEL 256
#define D_FFN   1024
#define LQ      21760
#define BATCH   2
#define M_ROWS  (BATCH * LQ)   // 43520

__device__ __constant__ int c_ST[4] = {0, 16384, 20480, 21504};

// ---------------- scratch ----------------
__device__ __nv_bfloat16 g_srcb [(size_t)M_ROWS * D_MODEL];
__device__ __nv_bfloat16 g_qsumb[(size_t)M_ROWS * D_MODEL];
__device__ __nv_bfloat16 g_value[(size_t)M_ROWS * D_MODEL];
__device__ float g_oa   [(size_t)M_ROWS * 384];   // oa; reused as t1 after sampling
__device__ __nv_bfloat16 g_samp [(size_t)M_ROWS * D_MODEL];
__device__ float g_h    [(size_t)M_ROWS * D_MODEL];
__device__ __nv_bfloat16 g_hb   [(size_t)M_ROWS * D_MODEL];
__device__ __nv_bfloat16 g_ffn  [(size_t)M_ROWS * D_FFN];
__device__ float g_t2   [(size_t)M_ROWS * D_MODEL];
__device__ __nv_bfloat16 g_WvalT [256 * 256];
__device__ __nv_bfloat16 g_WoaT  [384 * 256];
__device__ __nv_bfloat16 g_WoutT [256 * 256];
__device__ __nv_bfloat16 g_W1T   [1024 * 256];
__device__ __nv_bfloat16 g_W2T   [256 * 1024];

// ---------------- helpers ----------------
__device__ __forceinline__ uint32_t smem_u32(const void* p) {
    uint32_t a;
    asm("{ .reg .u64 t; cvta.to.shared.u64 t, %1; cvt.u32.u64 %0, t; }" : "=r"(a) : "l"(p));
    return a;
}
__device__ __forceinline__ void cpasync16(uint32_t dst, const void* src) {
    asm volatile("cp.async.cg.shared.global [%0], [%1], 16;" :: "r"(dst), "l"(src));
}
__device__ __forceinline__ void ldsm_x4(uint32_t& r0, uint32_t& r1, uint32_t& r2, uint32_t& r3, uint32_t addr) {
    asm volatile("ldmatrix.sync.aligned.m8n8.x4.shared.b16 {%0,%1,%2,%3}, [%4];"
        : "=r"(r0), "=r"(r1), "=r"(r2), "=r"(r3) : "r"(addr));
}
__device__ __forceinline__ void mma_bf16(float* d, const uint32_t* a, const uint32_t* b) {
    asm volatile("mma.sync.aligned.m16n8k16.row.col.f32.bf16.bf16.f32 "
        "{%0,%1,%2,%3}, {%4,%5,%6,%7}, {%8,%9}, {%0,%1,%2,%3};"
        : "+f"(d[0]), "+f"(d[1]), "+f"(d[2]), "+f"(d[3])
        : "r"(a[0]), "r"(a[1]), "r"(a[2]), "r"(a[3]), "r"(b[0]), "r"(b[1]));
}

// ---------------- tensor-core bf16 GEMM: BK=64, 3-stage cp.async (R10 proven) -------
template <bool RESF, bool RELUF, bool BF16OUT>
__global__ void __launch_bounds__(256, 2) gemm_mma(
    const __nv_bfloat16* __restrict__ A, const __nv_bfloat16* __restrict__ WT,
    const float* __restrict__ bias, const float* __restrict__ bias2, int nsplit,
    const float* __restrict__ res, void* __restrict__ Cout, int N, int K)
{
    extern __shared__ char dynsm[];
    const uint32_t smBase = smem_u32(dynsm);

    const int tid = threadIdx.x;
    const int lane = tid & 31;
    const int wid = tid >> 5;
    const int wm = wid & 1;
    const int wn = wid >> 1;
    const int bm = blockIdx.y * 128;
    const int bn = blockIdx.x * 128;

    const __nv_bfloat16* aG[4]; const __nv_bfloat16* bG[4];
    uint32_t sOff[4];
#pragma unroll
    for (int i = 0; i < 4; i++) {
        const int id = tid + i * 256;
        const int row = id >> 3, ck = id & 7;
        aG[i] = A  + (size_t)(bm + row) * K + ck * 8;
        bG[i] = WT + (size_t)(bn + row) * K + ck * 8;
        sOff[i] = row * 128 + ((ck ^ (row & 7)) * 16);
    }

    const int aRow = wm * 64 + (lane & 15);
    const int aCkH = lane >> 4;
    const int bRow = wn * 32 + ((lane >> 4) & 1) * 8 + (lane & 7);
    const int bCkH = (lane >> 3) & 1;

    float acc[4][4][4];
#pragma unroll
    for (int i = 0; i < 4; i++)
#pragma unroll
        for (int j = 0; j < 4; j++)
#pragma unroll
            for (int k = 0; k < 4; k++) acc[i][j][k] = 0.f;

    const int Cs = K >> 6;

#pragma unroll
    for (int i = 0; i < 4; i++) {
        cpasync16(smBase + sOff[i], aG[i]);
        cpasync16(smBase + 16384 + sOff[i], bG[i]);
    }
    asm volatile("cp.async.commit_group;" ::: "memory");
#pragma unroll
    for (int i = 0; i < 4; i++) {
        cpasync16(smBase + 32768 + sOff[i], aG[i] + 64);
        cpasync16(smBase + 32768 + 16384 + sOff[i], bG[i] + 64);
    }
    asm volatile("cp.async.commit_group;" ::: "memory");

    int st = 0, ldst = 2;
    for (int c = 0; c < Cs; ++c) {
        if (c == Cs - 1) asm volatile("cp.async.wait_group 0;" ::: "memory");
        else             asm volatile("cp.async.wait_group 1;" ::: "memory");
        __syncthreads();

        const uint32_t sA = smBase + (uint32_t)st * 32768;
        const uint32_t sB = sA + 16384;

#pragma unroll
        for (int ks = 0; ks < 4; ks++) {
            uint32_t af[4][4];
            uint32_t bfr[2][4];
#pragma unroll
            for (int mt = 0; mt < 4; mt++) {
                const int row = aRow + mt * 16;
                const int ck = ks * 2 + aCkH;
                ldsm_x4(af[mt][0], af[mt][1], af[mt][2], af[mt][3],
                        sA + row * 128 + ((ck ^ (row & 7)) * 16));
            }
#pragma unroll
            for (int np = 0; np < 2; np++) {
                const int row = bRow + np * 16;
                const int ck = ks * 2 + bCkH;
                ldsm_x4(bfr[np][0], bfr[np][1], bfr[np][2], bfr[np][3],
                        sB + row * 128 + ((ck ^ (row & 7)) * 16));
            }
#pragma unroll
            for (int mt = 0; mt < 4; mt++)
#pragma unroll
                for (int nt = 0; nt < 4; nt++)
                    mma_bf16(acc[mt][nt], af[mt], &bfr[nt >> 1][(nt & 1) * 2]);
        }

        if (c + 2 < Cs) {
            const int k0 = (c + 2) << 6;
            const uint32_t dA = smBase + (uint32_t)ldst * 32768;
#pragma unroll
            for (int i = 0; i < 4; i++) {
                cpasync16(dA + sOff[i], aG[i] + k0);
                cpasync16(dA + 16384 + sOff[i], bG[i] + k0);
            }
            asm volatile("cp.async.commit_group;" ::: "memory");
        }
        st = (st == 2) ? 0 : st + 1;
        ldst = (ldst == 2) ? 0 : ldst + 1;
    }

    const int r0base = bm + wm * 64 + (lane >> 2);
    const int cbase  = bn + wn * 32 + (lane & 3) * 2;
#pragma unroll
    for (int mt = 0; mt < 4; mt++) {
#pragma unroll
        for (int nt = 0; nt < 4; nt++) {
            const int col = cbase + nt * 8;
            const float bx = (col < nsplit) ? bias[col] : bias2[col - nsplit];
            const float by = (col + 1 < nsplit) ? bias[col + 1] : bias2[col + 1 - nsplit];
#pragma unroll
            for (int half = 0; half < 2; half++) {
                const int row = r0base + mt * 16 + half * 8;
                float vx = acc[mt][nt][half * 2 + 0] + bx;
                float vy = acc[mt][nt][half * 2 + 1] + by;
                if (RESF) {
                    const float* rp = res + (size_t)row * N + col;
                    vx += rp[0]; vy += rp[1];
                }
                if (RELUF) { vx = fmaxf(vx, 0.f); vy = fmaxf(vy, 0.f); }
                if (BF16OUT) {
                    __nv_bfloat162 bb = __floats2bfloat162_rn(vx, vy);
                    *(__nv_bfloat162*)((__nv_bfloat16*)Cout + (size_t)row * N + col) = bb;
                } else {
                    *(float2*)((float*)Cout + (size_t)row * N + col) = make_float2(vx, vy);
                }
            }
        }
    }
}

// ---------------- fused prep + weight transposes (single launch) ----------------
__device__ __forceinline__ void tr_tile(
    const float* __restrict__ W, __nv_bfloat16* __restrict__ WT,
    int K, int N, int kt, int nt, float (*tile)[33])
{
    const int k0 = kt * 32, n0 = nt * 32;
    const int tx = threadIdx.x & 31, ty = threadIdx.x >> 5;
#pragma unroll
    for (int r = 0; r < 4; r++)
        tile[ty + r * 8][tx] = W[(size_t)(k0 + ty + r * 8) * N + n0 + tx];
    __syncthreads();
#pragma unroll
    for (int r = 0; r < 4; r++)
        WT[(size_t)(n0 + ty + r * 8) * K + k0 + tx] = __float2bfloat16_rn(tile[tx][ty + r * 8]);
}

#define PREP_BLOCKS (M_ROWS * D_MODEL / 4 / 256)   // 10880

__global__ void __launch_bounds__(256) prep_all(
    const float* __restrict__ src, const float* __restrict__ pos,
    __nv_bfloat16* __restrict__ srcb, __nv_bfloat16* __restrict__ qsumb,
    const float* __restrict__ Wval, const float* __restrict__ Woff,
    const float* __restrict__ Wattn, const float* __restrict__ Wout,
    const float* __restrict__ W1, const float* __restrict__ W2,
    __nv_bfloat16* __restrict__ WvalT, __nv_bfloat16* __restrict__ WoaT,
    __nv_bfloat16* __restrict__ WoutT, __nv_bfloat16* __restrict__ W1T,
    __nv_bfloat16* __restrict__ W2T)
{
    __shared__ float tile[32][33];
    const int bx = blockIdx.x;
    if (bx < PREP_BLOCKS) {
        const int i = bx * 256 + threadIdx.x;
        float4 s = ((const float4*)src)[i];
        float4 p = ((const float4*)pos)[i];
        __nv_bfloat162* sb = (__nv_bfloat162*)srcb + i * 2;
        __nv_bfloat162* qb = (__nv_bfloat162*)qsumb + i * 2;
        sb[0] = __floats2bfloat162_rn(s.x, s.y);
        sb[1] = __floats2bfloat162_rn(s.z, s.w);
        qb[0] = __floats2bfloat162_rn(s.x + p.x, s.y + p.y);
        qb[1] = __floats2bfloat162_rn(s.z + p.z, s.w + p.w);
        return;
    }
    const int t = bx - PREP_BLOCKS;
    if (t < 64)       tr_tile(Wval, WvalT, 256, 256, t >> 3, t & 7, tile);
    else if (t < 128) { const int u = t - 64;  tr_tile(Woff, WoaT, 256, 256, u >> 3, u & 7, tile); }
    else if (t < 160) { const int u = t - 128; tr_tile(Wattn, WoaT + 256 * 256, 256, 128, u >> 2, u & 3, tile); }
    else if (t < 224) { const int u = t - 160; tr_tile(Wout, WoutT, 256, 256, u >> 3, u & 7, tile); }
    else if (t < 480) { const int u = t - 224; tr_tile(W1, W1T, 256, 1024, u >> 5, u & 31, tile); }
    else              { const int u = t - 480; tr_tile(W2, W2T, 1024, 256, u >> 3, u & 7, tile); }
}

// ---------------- sampler: warp per (bq, 4-head group); bf16x4 channels -------------
// 8-lane group per head; lane covers 4 channels via LDG.64 (uint2, token stride 64).
__global__ void __launch_bounds__(256) sample_bf4(
    const __nv_bfloat16* __restrict__ value,
    const float* __restrict__ oa,
    const float* __restrict__ refp, __nv_bfloat16* __restrict__ samp)
{
    const int warp_id = (blockIdx.x * blockDim.x + threadIdx.x) >> 5;  // over M_ROWS*2
    const int lane = threadIdx.x & 31;
    const int hg = warp_id & 1;
    const int bq = warp_id >> 1;
    const int b  = (bq >= LQ) ? 1 : 0;
    const int h  = hg * 4 + (lane >> 3);   // this group's head
    const int li = lane & 7;
    const int gsel = lane & 24;

    // ---- softmax over 16 logits within each 8-lane group (2 logits per lane) ----
    const float* al = oa + (size_t)bq * 384 + 256 + h * 16;
    const float l0 = al[li], l1 = al[li + 8];
    float mx = fmaxf(l0, l1);
#pragma unroll
    for (int o = 4; o; o >>= 1) mx = fmaxf(mx, __shfl_xor_sync(0xffffffffu, mx, o));
    const float e0 = __expf(l0 - mx), e1 = __expf(l1 - mx);
    float se = e0 + e1;
#pragma unroll
    for (int o = 4; o; o >>= 1) se += __shfl_xor_sync(0xffffffffu, se, o);
    const float inv_se = 1.f / se;

    // ---- params for points li (A) and li+8 (B) ----
    int cipA, cipB; uint32_t wA01, wA23, wB01, wB23;
    const float* op = oa + (size_t)bq * 384 + h * 32;
    const float* rp = refp + (size_t)bq * 8;
#pragma unroll
    for (int half = 0; half < 2; half++) {
        const int idx = li + half * 8;
        const int lvl = idx >> 2;
        const int Ww = 128 >> lvl;
        const float fW = (float)Ww;
        const float invW = 1.f / fW;
        const int st = c_ST[lvl];

        const float ox = op[idx * 2 + 0];
        const float oy = op[idx * 2 + 1];
        const float rx = rp[lvl * 2 + 0];
        const float ry = rp[lvl * 2 + 1];

        const float x = (rx + ox * invW) * fW - 0.5f;
        const float y = (ry + oy * invW) * fW - 0.5f;
        const float x0f = floorf(x), y0f = floorf(y);
        const int x0 = (int)x0f, y0 = (int)y0f;
        const float wx1 = x - x0f, wy1 = y - y0f;
        const float wx0 = 1.f - wx1, wy0 = 1.f - wy1;

        const float w = (half ? e1 : e0) * inv_se;
        const float vx0 = (x0 >= 0 && x0 < Ww) ? 1.f : 0.f;
        const float vx1 = (x0 + 1 >= 0 && x0 + 1 < Ww) ? 1.f : 0.f;
        const float vy0 = (y0 >= 0 && y0 < Ww) ? 1.f : 0.f;
        const float vy1 = (y0 + 1 >= 0 && y0 + 1 < Ww) ? 1.f : 0.f;

        const float cw0 = w * (wx0 * wy0) * (vx0 * vy0);
        const float cw1 = w * (wx1 * wy0) * (vx1 * vy0);
        const float cw2 = w * (wx0 * wy1) * (vx0 * vy1);
        const float cw3 = w * (wx1 * wy1) * (vx1 * vy1);

        const int xc0 = min(max(x0, 0), Ww - 1);
        const int xc1 = min(max(x0 + 1, 0), Ww - 1);
        const int yc0 = min(max(y0, 0), Ww - 1);
        const int yc1 = min(max(y0 + 1, 0), Ww - 1);
        const int cip = ((st + yc0 * Ww + xc0) << 2) | ((yc1 - yc0) << 1) | (xc1 - xc0);

        __half2 ha = __floats2half2_rn(cw0, cw1);
        __half2 hb2 = __floats2half2_rn(cw2, cw3);
        if (half == 0) { cipA = cip; wA01 = *(uint32_t*)&ha; wA23 = *(uint32_t*)&hb2; }
        else           { cipB = cip; wB01 = *(uint32_t*)&ha; wB23 = *(uint32_t*)&hb2; }
    }

    // ---- gather: lane covers channels [li*4 .. li*4+3]; token stride = 64 uint2 ----
    const uint2* v4 = (const uint2*)(value + (size_t)b * LQ * 256 + h * 32) + li;
    float p0 = 0.f, p1 = 0.f, p2 = 0.f, p3 = 0.f;
    float q0 = 0.f, q1 = 0.f, q2 = 0.f, q3 = 0.f;
#pragma unroll
    for (int p = 0; p < 16; p++) {
        const int src = gsel | (p & 7);
        const int pk  = __shfl_sync(0xffffffffu, (p < 8) ? cipA : cipB, src);
        const uint32_t wa = __shfl_sync(0xffffffffu, (p < 8) ? wA01 : wB01, src);
        const uint32_t wb = __shfl_sync(0xffffffffu, (p < 8) ? wA23 : wB23, src);
        const int tok = pk >> 2;
        const int dx  = pk & 1;
        const int dyW = ((pk >> 1) & 1) * (128 >> (p >> 2));

        const uint2 r00 = __ldg(v4 + (size_t)tok * 64);
        const uint2 r10 = __ldg(v4 + (size_t)(tok + dx) * 64);
        const uint2 r01 = __ldg(v4 + (size_t)(tok + dyW) * 64);
        const uint2 r11 = __ldg(v4 + (size_t)(tok + dyW + dx) * 64);

        const float2 w01 = __half22float2(*(const __half2*)&wa);
        const float2 w23 = __half22float2(*(const __half2*)&wb);

        float2 fa, fb;
        fa = __bfloat1622float2(*(const __nv_bfloat162*)&r00.x);
        fb = __bfloat1622float2(*(const __nv_bfloat162*)&r00.y);
        p0 += w01.x * fa.x; p1 += w01.x * fa.y; p2 += w01.x * fb.x; p3 += w01.x * fb.y;
        fa = __bfloat1622float2(*(const __nv_bfloat162*)&r10.x);
        fb = __bfloat1622float2(*(const __nv_bfloat162*)&r10.y);
        q0 += w01.y * fa.x; q1 += w01.y * fa.y; q2 += w01.y * fb.x; q3 += w01.y * fb.y;
        fa = __bfloat1622float2(*(const __nv_bfloat162*)&r01.x);
        fb = __bfloat1622float2(*(const __nv_bfloat162*)&r01.y);
        p0 += w23.x * fa.x; p1 += w23.x * fa.y; p2 += w23.x * fb.x; p3 += w23.x * fb.y;
        fa = __bfloat1622float2(*(const __nv_bfloat162*)&r11.x);
        fb = __bfloat1622float2(*(const __nv_bfloat162*)&r11.y);
        q0 += w23.y * fa.x; q1 += w23.y * fa.y; q2 += w23.y * fb.x; q3 += w23.y * fb.y;
    }
    __nv_bfloat162 o0 = __floats2bfloat162_rn(p0 + q0, p1 + q1);
    __nv_bfloat162 o1 = __floats2bfloat162_rn(p2 + q2, p3 + q3);
    uint2 ov; ov.x = *(uint32_t*)&o0; ov.y = *(uint32_t*)&o1;
    ((uint2*)(samp + (size_t)bq * 256 + h * 32))[li] = ov;
}

// ---------------- layernorm: one warp per row, float4 (R10) ----------------
template <bool WRBF>
__global__ void __launch_bounds__(256) ln4_kernel(
    const float* __restrict__ in, const float* __restrict__ g,
    const float* __restrict__ b, float* __restrict__ out, __nv_bfloat16* __restrict__ outbf)
{
    const int lane = threadIdx.x & 31;
    const size_t row = blockIdx.x * 8 + (threadIdx.x >> 5);
    const float4* in4 = (const float4*)(in + row * 256);
    const float4 A = in4[lane * 2], B4 = in4[lane * 2 + 1];

    float s = A.x + A.y + A.z + A.w + B4.x + B4.y + B4.z + B4.w;
#pragma unroll
    for (int o = 16; o; o >>= 1) s += __shfl_xor_sync(0xffffffffu, s, o);
    const float mu = s * (1.f / 256.f);

    float4 dA, dB;
    dA.x = A.x - mu; dA.y = A.y - mu; dA.z = A.z - mu; dA.w = A.w - mu;
    dB.x = B4.x - mu; dB.y = B4.y - mu; dB.z = B4.z - mu; dB.w = B4.w - mu;
    float v = dA.x*dA.x + dA.y*dA.y + dA.z*dA.z + dA.w*dA.w
            + dB.x*dB.x + dB.y*dB.y + dB.z*dB.z + dB.w*dB.w;
#pragma unroll
    for (int o = 16; o; o >>= 1) v += __shfl_xor_sync(0xffffffffu, v, o);
    const float rstd = rsqrtf(v * (1.f / 256.f) + 1e-5f);

    const float4 gA = ((const float4*)g)[lane * 2], gB = ((const float4*)g)[lane * 2 + 1];
    const float4 bA = ((const float4*)b)[lane * 2], bB = ((const float4*)b)[lane * 2 + 1];
    float4 yA, yB;
    yA.x = dA.x * rstd * gA.x + bA.x; yA.y = dA.y * rstd * gA.y + bA.y;
    yA.z = dA.z * rstd * gA.z + bA.z; yA.w = dA.w * rstd * gA.w + bA.w;
    yB.x = dB.x * rstd * gB.x + bB.x; yB.y = dB.y * rstd * gB.y + bB.y;
    yB.z = dB.z * rstd * gB.z + bB.z; yB.w = dB.w * rstd * gB.w + bB.w;

    float4* o4 = (float4*)(out + row * 256);
    o4[lane * 2] = yA; o4[lane * 2 + 1] = yB;
    if (WRBF) {
        __nv_bfloat162* r2 = (__nv_bfloat162*)(outbf + row * 256) + lane * 4;
        r2[0] = __floats2bfloat162_rn(yA.x, yA.y);
        r2[1] = __floats2bfloat162_rn(yA.z, yA.w);
        r2[2] = __floats2bfloat162_rn(yB.x, yB.y);
        r2[3] = __floats2bfloat162_rn(yB.z, yB.w);
    }
}

// ---------------- launch ----------------
extern "C" void kernel_launch(void* const* d_in, const int* in_sizes, int n_in,
                              void* d_out, int out_size)
{
    const float* src    = (const float*)d_in[0];
    const float* pos    = (const float*)d_in[1];
    const float* refp   = (const float*)d_in[2];
    const float* W_off  = (const float*)d_in[3];
    const float* b_off  = (const float*)d_in[4];
    const float* W_attn = (const float*)d_in[5];
    const float* b_attn = (const float*)d_in[6];
    const float* W_val  = (const float*)d_in[7];
    const float* b_val  = (const float*)d_in[8];
    const float* W_out  = (const float*)d_in[9];
    const float* b_out  = (const float*)d_in[10];
    const float* ln1_g  = (const float*)d_in[11];
    const float* ln1_b  = (const float*)d_in[12];
    const float* W1     = (const float*)d_in[13];
    const float* b1     = (const float*)d_in[14];
    const float* W2     = (const float*)d_in[15];
    const float* b2     = (const float*)d_in[16];
    const float* ln2_g  = (const float*)d_in[17];
    const float* ln2_b  = (const float*)d_in[18];
    float* out = (float*)d_out;

    __nv_bfloat16 *p_srcb, *p_qsumb, *p_value, *p_samp, *p_hb, *p_ffn;
    __nv_bfloat16 *p_WvalT, *p_WoaT, *p_WoutT, *p_W1T, *p_W2T;
    float *p_oa, *p_h, *p_t2;
    cudaGetSymbolAddress((void**)&p_srcb,  g_srcb);
    cudaGetSymbolAddress((void**)&p_qsumb, g_qsumb);
    cudaGetSymbolAddress((void**)&p_value, g_value);
    cudaGetSymbolAddress((void**)&p_oa,    g_oa);
    cudaGetSymbolAddress((void**)&p_samp,  g_samp);
    cudaGetSymbolAddress((void**)&p_h,     g_h);
    cudaGetSymbolAddress((void**)&p_hb,    g_hb);
    cudaGetSymbolAddress((void**)&p_ffn,   g_ffn);
    cudaGetSymbolAddress((void**)&p_t2,    g_t2);
    cudaGetSymbolAddress((void**)&p_WvalT, g_WvalT);
    cudaGetSymbolAddress((void**)&p_WoaT,  g_WoaT);
    cudaGetSymbolAddress((void**)&p_WoutT, g_WoutT);
    cudaGetSymbolAddress((void**)&p_W1T,   g_W1T);
    cudaGetSymbolAddress((void**)&p_W2T,   g_W2T);

    float* p_t1 = p_oa;   // reuse: oa dead after sampling

    const int SMEM_BYTES = 3 * 32768;  // 96 KB
    cudaFuncSetAttribute(gemm_mma<false, false, true >, cudaFuncAttributeMaxDynamicSharedMemorySize, SMEM_BYTES);
    cudaFuncSetAttribute(gemm_mma<false, false, false>, cudaFuncAttributeMaxDynamicSharedMemorySize, SMEM_BYTES);
    cudaFuncSetAttribute(gemm_mma<true,  false, false>, cudaFuncAttributeMaxDynamicSharedMemorySize, SMEM_BYTES);
    cudaFuncSetAttribute(gemm_mma<false, true,  true >, cudaFuncAttributeMaxDynamicSharedMemorySize, SMEM_BYTES);

    const int M = M_ROWS;
    const int MT = M / 128;  // 340
    const int BIG = 1 << 30;

    // 0: prep + all weight transposes (fused)
    prep_all<<<PREP_BLOCKS + 736, 256>>>(src, pos, p_srcb, p_qsumb,
        W_val, W_off, W_attn, W_out, W1, W2,
        p_WvalT, p_WoaT, p_WoutT, p_W1T, p_W2T);
    // 1: value (bf16) = src @ W_val + b_val
    gemm_mma<false, false, true><<<dim3(2, MT), 256, SMEM_BYTES>>>(
        p_srcb, p_WvalT, b_val, b_val, BIG, nullptr, p_value, 256, 256);
    // 2: oa (fp32) = (src+pos) @ [W_off|W_attn] + [b_off|b_attn]
    gemm_mma<false, false, false><<<dim3(3, MT), 256, SMEM_BYTES>>>(
        p_qsumb, p_WoaT, b_off, b_attn, 256, nullptr, p_oa, 384, 256);
    // 3: sampling (4 heads per warp)
    sample_bf4<<<M * 2 / 8, 256>>>(p_value, p_oa, refp, p_samp);
    // 4: t1 = samp @ W_out + b_out + src  (t1 aliases oa)
    gemm_mma<true, false, false><<<dim3(2, MT), 256, SMEM_BYTES>>>(
        p_samp, p_WoutT, b_out, b_out, BIG, src, p_t1, 256, 256);
    // 5: h = LN1(t1) (+ bf16 copy hb)
    ln4_kernel<true><<<M / 8, 256>>>(p_t1, ln1_g, ln1_b, p_h, p_hb);
    // 6: ffn = relu(h @ W1 + b1)  (bf16)
    gemm_mma<false, true, true><<<dim3(8, MT), 256, SMEM_BYTES>>>(
        p_hb, p_W1T, b1, b1, BIG, nullptr, p_ffn, 1024, 256);
    // 7: t2 = ffn @ W2 + b2 + h
    gemm_mma<true, false, false><<<dim3(2, MT), 256, SMEM_BYTES>>>(
        p_ffn, p_W2T, b2, b2, BIG, p_h, p_t2, 256, 1024);
    // 8: out = LN2(t2)
    ln4_kernel<false><<<M / 8, 256>>>(p_t2, ln2_g, ln2_b, out, nullptr);
}

// round 17
// speedup vs baseline: 1.3189x; 1.0876x over previous
#include <cuda_runtime.h>
#include <cuda_bf16.h>
#include <cuda_fp16.h>
#include <math.h>
#include <stdint.h>

// ---------------- problem constants ----------------
#define D_MODEL 256
#define D_FFN   1024
#define LQ      21760
#define BATCH   2
#define M_ROWS  (BATCH * LQ)   // 43520

__device__ __constant__ int c_ST[4] = {0, 16384, 20480, 21504};

// ---------------- scratch ----------------
__device__ __nv_bfloat16 g_srcb [(size_t)M_ROWS * D_MODEL];
__device__ __nv_bfloat16 g_qsumb[(size_t)M_ROWS * D_MODEL];
__device__ __nv_bfloat16 g_value[(size_t)M_ROWS * D_MODEL];
__device__ float g_oa   [(size_t)M_ROWS * 384];   // oa; reused as t1 after sampling
__device__ __nv_bfloat16 g_samp [(size_t)M_ROWS * D_MODEL];
__device__ float g_h    [(size_t)M_ROWS * D_MODEL];
__device__ __nv_bfloat16 g_hb   [(size_t)M_ROWS * D_MODEL];
__device__ __nv_bfloat16 g_ffn  [(size_t)M_ROWS * D_FFN];
__device__ float g_t2   [(size_t)M_ROWS * D_MODEL];
__device__ __nv_bfloat16 g_WvalT [256 * 256];
__device__ __nv_bfloat16 g_WoaT  [384 * 256];
__device__ __nv_bfloat16 g_WoutT [256 * 256];
__device__ __nv_bfloat16 g_W1T   [1024 * 256];
__device__ __nv_bfloat16 g_W2T   [256 * 1024];

// ---------------- helpers ----------------
__device__ __forceinline__ uint32_t smem_u32(const void* p) {
    uint32_t a;
    asm("{ .reg .u64 t; cvta.to.shared.u64 t, %1; cvt.u32.u64 %0, t; }" : "=r"(a) : "l"(p));
    return a;
}
__device__ __forceinline__ void cpasync16(uint32_t dst, const void* src) {
    asm volatile("cp.async.cg.shared.global [%0], [%1], 16;" :: "r"(dst), "l"(src));
}
__device__ __forceinline__ void ldsm_x4(uint32_t& r0, uint32_t& r1, uint32_t& r2, uint32_t& r3, uint32_t addr) {
    asm volatile("ldmatrix.sync.aligned.m8n8.x4.shared.b16 {%0,%1,%2,%3}, [%4];"
        : "=r"(r0), "=r"(r1), "=r"(r2), "=r"(r3) : "r"(addr));
}
__device__ __forceinline__ void mma_bf16(float* d, const uint32_t* a, const uint32_t* b) {
    asm volatile("mma.sync.aligned.m16n8k16.row.col.f32.bf16.bf16.f32 "
        "{%0,%1,%2,%3}, {%4,%5,%6,%7}, {%8,%9}, {%0,%1,%2,%3};"
        : "+f"(d[0]), "+f"(d[1]), "+f"(d[2]), "+f"(d[3])
        : "r"(a[0]), "r"(a[1]), "r"(a[2]), "r"(a[3]), "r"(b[0]), "r"(b[1]));
}
// packed f32x2 FMA (SASS FFMA2), PTX ISA 8.6 sm_100+
__device__ __forceinline__ void fma2(unsigned long long& acc, unsigned long long a, unsigned long long w) {
    asm("fma.rn.f32x2 %0, %1, %2, %0;" : "+l"(acc) : "l"(a), "l"(w));
}
__device__ __forceinline__ unsigned long long bf2_f32x2(uint32_t v) {
    const uint32_t lo = v << 16;
    const uint32_t hi = v & 0xffff0000u;
    unsigned long long r;
    asm("mov.b64 %0, {%1, %2};" : "=l"(r) : "r"(lo), "r"(hi));
    return r;
}
__device__ __forceinline__ unsigned long long dupf(float w) {
    unsigned long long r;
    asm("mov.b64 %0, {%1, %1};" : "=l"(r) : "f"(w));
    return r;
}

// ---------------- tensor-core bf16 GEMM: BK=64, 3-stage cp.async (proven) ----------
template <bool RESF, bool RELUF, bool BF16OUT>
__global__ void __launch_bounds__(256, 2) gemm_mma(
    const __nv_bfloat16* __restrict__ A, const __nv_bfloat16* __restrict__ WT,
    const float* __restrict__ bias, const float* __restrict__ bias2, int nsplit,
    const float* __restrict__ res, void* __restrict__ Cout, int N, int K)
{
    extern __shared__ char dynsm[];
    const uint32_t smBase = smem_u32(dynsm);

    const int tid = threadIdx.x;
    const int lane = tid & 31;
    const int wid = tid >> 5;
    const int wm = wid & 1;
    const int wn = wid >> 1;
    const int bm = blockIdx.y * 128;
    const int bn = blockIdx.x * 128;

    const __nv_bfloat16* aG[4]; const __nv_bfloat16* bG[4];
    uint32_t sOff[4];
#pragma unroll
    for (int i = 0; i < 4; i++) {
        const int id = tid + i * 256;
        const int row = id >> 3, ck = id & 7;
        aG[i] = A  + (size_t)(bm + row) * K + ck * 8;
        bG[i] = WT + (size_t)(bn + row) * K + ck * 8;
        sOff[i] = row * 128 + ((ck ^ (row & 7)) * 16);
    }

    const int aRow = wm * 64 + (lane & 15);
    const int aCkH = lane >> 4;
    const int bRow = wn * 32 + ((lane >> 4) & 1) * 8 + (lane & 7);
    const int bCkH = (lane >> 3) & 1;

    float acc[4][4][4];
#pragma unroll
    for (int i = 0; i < 4; i++)
#pragma unroll
        for (int j = 0; j < 4; j++)
#pragma unroll
            for (int k = 0; k < 4; k++) acc[i][j][k] = 0.f;

    const int Cs = K >> 6;

#pragma unroll
    for (int i = 0; i < 4; i++) {
        cpasync16(smBase + sOff[i], aG[i]);
        cpasync16(smBase + 16384 + sOff[i], bG[i]);
    }
    asm volatile("cp.async.commit_group;" ::: "memory");
#pragma unroll
    for (int i = 0; i < 4; i++) {
        cpasync16(smBase + 32768 + sOff[i], aG[i] + 64);
        cpasync16(smBase + 32768 + 16384 + sOff[i], bG[i] + 64);
    }
    asm volatile("cp.async.commit_group;" ::: "memory");

    int st = 0, ldst = 2;
    for (int c = 0; c < Cs; ++c) {
        if (c == Cs - 1) asm volatile("cp.async.wait_group 0;" ::: "memory");
        else             asm volatile("cp.async.wait_group 1;" ::: "memory");
        __syncthreads();

        const uint32_t sA = smBase + (uint32_t)st * 32768;
        const uint32_t sB = sA + 16384;

#pragma unroll
        for (int ks = 0; ks < 4; ks++) {
            uint32_t af[4][4];
            uint32_t bfr[2][4];
#pragma unroll
            for (int mt = 0; mt < 4; mt++) {
                const int row = aRow + mt * 16;
                const int ck = ks * 2 + aCkH;
                ldsm_x4(af[mt][0], af[mt][1], af[mt][2], af[mt][3],
                        sA + row * 128 + ((ck ^ (row & 7)) * 16));
            }
#pragma unroll
            for (int np = 0; np < 2; np++) {
                const int row = bRow + np * 16;
                const int ck = ks * 2 + bCkH;
                ldsm_x4(bfr[np][0], bfr[np][1], bfr[np][2], bfr[np][3],
                        sB + row * 128 + ((ck ^ (row & 7)) * 16));
            }
#pragma unroll
            for (int mt = 0; mt < 4; mt++)
#pragma unroll
                for (int nt = 0; nt < 4; nt++)
                    mma_bf16(acc[mt][nt], af[mt], &bfr[nt >> 1][(nt & 1) * 2]);
        }

        if (c + 2 < Cs) {
            const int k0 = (c + 2) << 6;
            const uint32_t dA = smBase + (uint32_t)ldst * 32768;
#pragma unroll
            for (int i = 0; i < 4; i++) {
                cpasync16(dA + sOff[i], aG[i] + k0);
                cpasync16(dA + 16384 + sOff[i], bG[i] + k0);
            }
            asm volatile("cp.async.commit_group;" ::: "memory");
        }
        st = (st == 2) ? 0 : st + 1;
        ldst = (ldst == 2) ? 0 : ldst + 1;
    }

    const int r0base = bm + wm * 64 + (lane >> 2);
    const int cbase  = bn + wn * 32 + (lane & 3) * 2;
#pragma unroll
    for (int mt = 0; mt < 4; mt++) {
#pragma unroll
        for (int nt = 0; nt < 4; nt++) {
            const int col = cbase + nt * 8;
            const float bx = (col < nsplit) ? bias[col] : bias2[col - nsplit];
            const float by = (col + 1 < nsplit) ? bias[col + 1] : bias2[col + 1 - nsplit];
#pragma unroll
            for (int half = 0; half < 2; half++) {
                const int row = r0base + mt * 16 + half * 8;
                float vx = acc[mt][nt][half * 2 + 0] + bx;
                float vy = acc[mt][nt][half * 2 + 1] + by;
                if (RESF) {
                    const float* rp = res + (size_t)row * N + col;
                    vx += rp[0]; vy += rp[1];
                }
                if (RELUF) { vx = fmaxf(vx, 0.f); vy = fmaxf(vy, 0.f); }
                if (BF16OUT) {
                    __nv_bfloat162 bb = __floats2bfloat162_rn(vx, vy);
                    *(__nv_bfloat162*)((__nv_bfloat16*)Cout + (size_t)row * N + col) = bb;
                } else {
                    *(float2*)((float*)Cout + (size_t)row * N + col) = make_float2(vx, vy);
                }
            }
        }
    }
}

// ---------------- fused prep + weight transposes (single launch) ----------------
__device__ __forceinline__ void tr_tile(
    const float* __restrict__ W, __nv_bfloat16* __restrict__ WT,
    int K, int N, int kt, int nt, float (*tile)[33])
{
    const int k0 = kt * 32, n0 = nt * 32;
    const int tx = threadIdx.x & 31, ty = threadIdx.x >> 5;
#pragma unroll
    for (int r = 0; r < 4; r++)
        tile[ty + r * 8][tx] = W[(size_t)(k0 + ty + r * 8) * N + n0 + tx];
    __syncthreads();
#pragma unroll
    for (int r = 0; r < 4; r++)
        WT[(size_t)(n0 + ty + r * 8) * K + k0 + tx] = __float2bfloat16_rn(tile[tx][ty + r * 8]);
}

#define PREP_BLOCKS (M_ROWS * D_MODEL / 4 / 256)   // 10880

__global__ void __launch_bounds__(256) prep_all(
    const float* __restrict__ src, const float* __restrict__ pos,
    __nv_bfloat16* __restrict__ srcb, __nv_bfloat16* __restrict__ qsumb,
    const float* __restrict__ Wval, const float* __restrict__ Woff,
    const float* __restrict__ Wattn, const float* __restrict__ Wout,
    const float* __restrict__ W1, const float* __restrict__ W2,
    __nv_bfloat16* __restrict__ WvalT, __nv_bfloat16* __restrict__ WoaT,
    __nv_bfloat16* __restrict__ WoutT, __nv_bfloat16* __restrict__ W1T,
    __nv_bfloat16* __restrict__ W2T)
{
    __shared__ float tile[32][33];
    const int bx = blockIdx.x;
    if (bx < PREP_BLOCKS) {
        const int i = bx * 256 + threadIdx.x;
        float4 s = ((const float4*)src)[i];
        float4 p = ((const float4*)pos)[i];
        __nv_bfloat162* sb = (__nv_bfloat162*)srcb + i * 2;
        __nv_bfloat162* qb = (__nv_bfloat162*)qsumb + i * 2;
        sb[0] = __floats2bfloat162_rn(s.x, s.y);
        sb[1] = __floats2bfloat162_rn(s.z, s.w);
        qb[0] = __floats2bfloat162_rn(s.x + p.x, s.y + p.y);
        qb[1] = __floats2bfloat162_rn(s.z + p.z, s.w + p.w);
        return;
    }
    const int t = bx - PREP_BLOCKS;
    if (t < 64)       tr_tile(Wval, WvalT, 256, 256, t >> 3, t & 7, tile);
    else if (t < 128) { const int u = t - 64;  tr_tile(Woff, WoaT, 256, 256, u >> 3, u & 7, tile); }
    else if (t < 160) { const int u = t - 128; tr_tile(Wattn, WoaT + 256 * 256, 256, 128, u >> 2, u & 3, tile); }
    else if (t < 224) { const int u = t - 160; tr_tile(Wout, WoutT, 256, 256, u >> 3, u & 7, tile); }
    else if (t < 480) { const int u = t - 224; tr_tile(W1, W1T, 256, 1024, u >> 5, u & 31, tile); }
    else              { const int u = t - 480; tr_tile(W2, W2T, 1024, 256, u >> 3, u & 7, tile); }
}

// ---------------- sampler: warp per token (8 heads); 4-lane group per head ----------
// lane: h = lane>>2, li = lane&3 (uint4 quad -> channels li*8..li*8+7).
// Lane li owns all 4 points of level li (shared level constants).
// Accumulation via packed fma.rn.f32x2 (FFMA2), fp32 exact, 2 accs/channel.
__global__ void __launch_bounds__(256) sample_bf8(
    const __nv_bfloat16* __restrict__ value,
    const float* __restrict__ oa,
    const float* __restrict__ refp, __nv_bfloat16* __restrict__ samp)
{
    const int bq = (blockIdx.x * blockDim.x + threadIdx.x) >> 5;  // warp per token
    const int lane = threadIdx.x & 31;
    const int b  = (bq >= LQ) ? 1 : 0;
    const int h  = lane >> 2;
    const int li = lane & 3;        // level / quad index
    const int gsel = lane & 28;

    // ---- softmax over 16 logits per head: lane li holds logits 4li..4li+3 ----
    const float* al = oa + (size_t)bq * 384 + 256 + h * 16;
    const float4 lg = *(const float4*)(al + li * 4);
    float mx = fmaxf(fmaxf(lg.x, lg.y), fmaxf(lg.z, lg.w));
    mx = fmaxf(mx, __shfl_xor_sync(0xffffffffu, mx, 1));
    mx = fmaxf(mx, __shfl_xor_sync(0xffffffffu, mx, 2));
    float es[4];
    es[0] = __expf(lg.x - mx); es[1] = __expf(lg.y - mx);
    es[2] = __expf(lg.z - mx); es[3] = __expf(lg.w - mx);
    float se = (es[0] + es[1]) + (es[2] + es[3]);
    se += __shfl_xor_sync(0xffffffffu, se, 1);
    se += __shfl_xor_sync(0xffffffffu, se, 2);
    const float inv_se = 1.f / se;

    // ---- params for 4 points of level li ----
    int cip[4]; uint32_t w01[4], w23[4];
    {
        const int Ww = 128 >> li;
        const float fW = (float)Ww;
        const float invW = 1.f / fW;
        const int st = c_ST[li];
        const float* rp = refp + (size_t)bq * 8;
        const float rx = rp[li * 2 + 0];
        const float ry = rp[li * 2 + 1];
        const float* op = oa + (size_t)bq * 384 + h * 32 + li * 8;
        const float4 o01 = *(const float4*)op;
        const float4 o23 = *(const float4*)(op + 4);
        const float oxs[4] = {o01.x, o01.z, o23.x, o23.z};
        const float oys[4] = {o01.y, o01.w, o23.y, o23.w};
#pragma unroll
        for (int j = 0; j < 4; j++) {
            const float x = (rx + oxs[j] * invW) * fW - 0.5f;
            const float y = (ry + oys[j] * invW) * fW - 0.5f;
            const float x0f = floorf(x), y0f = floorf(y);
            const int x0 = (int)x0f, y0 = (int)y0f;
            const float wx1 = x - x0f, wy1 = y - y0f;
            const float wx0 = 1.f - wx1, wy0 = 1.f - wy1;

            const float w = es[j] * inv_se;
            const float vx0 = (x0 >= 0 && x0 < Ww) ? 1.f : 0.f;
            const float vx1 = (x0 + 1 >= 0 && x0 + 1 < Ww) ? 1.f : 0.f;
            const float vy0 = (y0 >= 0 && y0 < Ww) ? 1.f : 0.f;
            const float vy1 = (y0 + 1 >= 0 && y0 + 1 < Ww) ? 1.f : 0.f;

            const float cw0 = w * (wx0 * wy0) * (vx0 * vy0);
            const float cw1 = w * (wx1 * wy0) * (vx1 * vy0);
            const float cw2 = w * (wx0 * wy1) * (vx0 * vy1);
            const float cw3 = w * (wx1 * wy1) * (vx1 * vy1);

            const int xc0 = min(max(x0, 0), Ww - 1);
            const int xc1 = min(max(x0 + 1, 0), Ww - 1);
            const int yc0 = min(max(y0, 0), Ww - 1);
            const int yc1 = min(max(y0 + 1, 0), Ww - 1);
            cip[j] = ((st + yc0 * Ww + xc0) << 2) | ((yc1 - yc0) << 1) | (xc1 - xc0);

            __half2 ha = __floats2half2_rn(cw0, cw1);
            __half2 hb2 = __floats2half2_rn(cw2, cw3);
            w01[j] = *(uint32_t*)&ha;
            w23[j] = *(uint32_t*)&hb2;
        }
    }

    // ---- gather: lane covers 8 channels (uint4); token stride = 32 uint4 ----
    const uint4* v16 = (const uint4*)(value + (size_t)b * LQ * 256) + h * 4 + li;
    unsigned long long ap[4] = {0, 0, 0, 0};
    unsigned long long aq[4] = {0, 0, 0, 0};
#pragma unroll
    for (int p = 0; p < 16; p++) {
        const int src = gsel | (p >> 2);
        const int j = p & 3;
        const int pk = __shfl_sync(0xffffffffu, cip[j], src);
        const uint32_t wa = __shfl_sync(0xffffffffu, w01[j], src);
        const uint32_t wb = __shfl_sync(0xffffffffu, w23[j], src);
        const int tok = pk >> 2;
        const int dx  = pk & 1;
        const int dyW = ((pk >> 1) & 1) * (128 >> (p >> 2));

        const uint4 r00 = __ldg(v16 + (size_t)tok * 32);
        const uint4 r10 = __ldg(v16 + (size_t)(tok + dx) * 32);
        const uint4 r01 = __ldg(v16 + (size_t)(tok + dyW) * 32);
        const uint4 r11 = __ldg(v16 + (size_t)(tok + dyW + dx) * 32);

        const float2 wf01 = __half22float2(*(const __half2*)&wa);
        const float2 wf23 = __half22float2(*(const __half2*)&wb);
        const unsigned long long W00 = dupf(wf01.x);
        const unsigned long long W10 = dupf(wf01.y);
        const unsigned long long W01 = dupf(wf23.x);
        const unsigned long long W11 = dupf(wf23.y);

        fma2(ap[0], bf2_f32x2(r00.x), W00); fma2(ap[1], bf2_f32x2(r00.y), W00);
        fma2(ap[2], bf2_f32x2(r00.z), W00); fma2(ap[3], bf2_f32x2(r00.w), W00);
        fma2(aq[0], bf2_f32x2(r10.x), W10); fma2(aq[1], bf2_f32x2(r10.y), W10);
        fma2(aq[2], bf2_f32x2(r10.z), W10); fma2(aq[3], bf2_f32x2(r10.w), W10);
        fma2(ap[0], bf2_f32x2(r01.x), W01); fma2(ap[1], bf2_f32x2(r01.y), W01);
        fma2(ap[2], bf2_f32x2(r01.z), W01); fma2(ap[3], bf2_f32x2(r01.w), W01);
        fma2(aq[0], bf2_f32x2(r11.x), W11); fma2(aq[1], bf2_f32x2(r11.y), W11);
        fma2(aq[2], bf2_f32x2(r11.z), W11); fma2(aq[3], bf2_f32x2(r11.w), W11);
    }

    uint4 ov;
    uint32_t* ow = (uint32_t*)&ov;
#pragma unroll
    for (int k = 0; k < 4; k++) {
        float plo, phi, qlo, qhi;
        asm("mov.b64 {%0, %1}, %2;" : "=f"(plo), "=f"(phi) : "l"(ap[k]));
        asm("mov.b64 {%0, %1}, %2;" : "=f"(qlo), "=f"(qhi) : "l"(aq[k]));
        __nv_bfloat162 o = __floats2bfloat162_rn(plo + qlo, phi + qhi);
        ow[k] = *(uint32_t*)&o;
    }
    ((uint4*)(samp + (size_t)bq * 256 + h * 32))[li] = ov;
}

// ---------------- layernorm: one warp per row, float4 ----------------
template <bool WRBF>
__global__ void __launch_bounds__(256) ln4_kernel(
    const float* __restrict__ in, const float* __restrict__ g,
    const float* __restrict__ b, float* __restrict__ out, __nv_bfloat16* __restrict__ outbf)
{
    const int lane = threadIdx.x & 31;
    const size_t row = blockIdx.x * 8 + (threadIdx.x >> 5);
    const float4* in4 = (const float4*)(in + row * 256);
    const float4 A = in4[lane * 2], B4 = in4[lane * 2 + 1];

    float s = A.x + A.y + A.z + A.w + B4.x + B4.y + B4.z + B4.w;
#pragma unroll
    for (int o = 16; o; o >>= 1) s += __shfl_xor_sync(0xffffffffu, s, o);
    const float mu = s * (1.f / 256.f);

    float4 dA, dB;
    dA.x = A.x - mu; dA.y = A.y - mu; dA.z = A.z - mu; dA.w = A.w - mu;
    dB.x = B4.x - mu; dB.y = B4.y - mu; dB.z = B4.z - mu; dB.w = B4.w - mu;
    float v = dA.x*dA.x + dA.y*dA.y + dA.z*dA.z + dA.w*dA.w
            + dB.x*dB.x + dB.y*dB.y + dB.z*dB.z + dB.w*dB.w;
#pragma unroll
    for (int o = 16; o; o >>= 1) v += __shfl_xor_sync(0xffffffffu, v, o);
    const float rstd = rsqrtf(v * (1.f / 256.f) + 1e-5f);

    const float4 gA = ((const float4*)g)[lane * 2], gB = ((const float4*)g)[lane * 2 + 1];
    const float4 bA = ((const float4*)b)[lane * 2], bB = ((const float4*)b)[lane * 2 + 1];
    float4 yA, yB;
    yA.x = dA.x * rstd * gA.x + bA.x; yA.y = dA.y * rstd * gA.y + bA.y;
    yA.z = dA.z * rstd * gA.z + bA.z; yA.w = dA.w * rstd * gA.w + bA.w;
    yB.x = dB.x * rstd * gB.x + bB.x; yB.y = dB.y * rstd * gB.y + bB.y;
    yB.z = dB.z * rstd * gB.z + bB.z; yB.w = dB.w * rstd * gB.w + bB.w;

    float4* o4 = (float4*)(out + row * 256);
    o4[lane * 2] = yA; o4[lane * 2 + 1] = yB;
    if (WRBF) {
        __nv_bfloat162* r2 = (__nv_bfloat162*)(outbf + row * 256) + lane * 4;
        r2[0] = __floats2bfloat162_rn(yA.x, yA.y);
        r2[1] = __floats2bfloat162_rn(yA.z, yA.w);
        r2[2] = __floats2bfloat162_rn(yB.x, yB.y);
        r2[3] = __floats2bfloat162_rn(yB.z, yB.w);
    }
}

// ---------------- launch ----------------
extern "C" void kernel_launch(void* const* d_in, const int* in_sizes, int n_in,
                              void* d_out, int out_size)
{
    const float* src    = (const float*)d_in[0];
    const float* pos    = (const float*)d_in[1];
    const float* refp   = (const float*)d_in[2];
    const float* W_off  = (const float*)d_in[3];
    const float* b_off  = (const float*)d_in[4];
    const float* W_attn = (const float*)d_in[5];
    const float* b_attn = (const float*)d_in[6];
    const float* W_val  = (const float*)d_in[7];
    const float* b_val  = (const float*)d_in[8];
    const float* W_out  = (const float*)d_in[9];
    const float* b_out  = (const float*)d_in[10];
    const float* ln1_g  = (const float*)d_in[11];
    const float* ln1_b  = (const float*)d_in[12];
    const float* W1     = (const float*)d_in[13];
    const float* b1     = (const float*)d_in[14];
    const float* W2     = (const float*)d_in[15];
    const float* b2     = (const float*)d_in[16];
    const float* ln2_g  = (const float*)d_in[17];
    const float* ln2_b  = (const float*)d_in[18];
    float* out = (float*)d_out;

    __nv_bfloat16 *p_srcb, *p_qsumb, *p_value, *p_samp, *p_hb, *p_ffn;
    __nv_bfloat16 *p_WvalT, *p_WoaT, *p_WoutT, *p_W1T, *p_W2T;
    float *p_oa, *p_h, *p_t2;
    cudaGetSymbolAddress((void**)&p_srcb,  g_srcb);
    cudaGetSymbolAddress((void**)&p_qsumb, g_qsumb);
    cudaGetSymbolAddress((void**)&p_value, g_value);
    cudaGetSymbolAddress((void**)&p_oa,    g_oa);
    cudaGetSymbolAddress((void**)&p_samp,  g_samp);
    cudaGetSymbolAddress((void**)&p_h,     g_h);
    cudaGetSymbolAddress((void**)&p_hb,    g_hb);
    cudaGetSymbolAddress((void**)&p_ffn,   g_ffn);
    cudaGetSymbolAddress((void**)&p_t2,    g_t2);
    cudaGetSymbolAddress((void**)&p_WvalT, g_WvalT);
    cudaGetSymbolAddress((void**)&p_WoaT,  g_WoaT);
    cudaGetSymbolAddress((void**)&p_WoutT, g_WoutT);
    cudaGetSymbolAddress((void**)&p_W1T,   g_W1T);
    cudaGetSymbolAddress((void**)&p_W2T,   g_W2T);

    float* p_t1 = p_oa;   // reuse: oa dead after sampling

    const int SMEM_BYTES = 3 * 32768;  // 96 KB
    cudaFuncSetAttribute(gemm_mma<false, false, true >, cudaFuncAttributeMaxDynamicSharedMemorySize, SMEM_BYTES);
    cudaFuncSetAttribute(gemm_mma<false, false, false>, cudaFuncAttributeMaxDynamicSharedMemorySize, SMEM_BYTES);
    cudaFuncSetAttribute(gemm_mma<true,  false, false>, cudaFuncAttributeMaxDynamicSharedMemorySize, SMEM_BYTES);
    cudaFuncSetAttribute(gemm_mma<false, true,  true >, cudaFuncAttributeMaxDynamicSharedMemorySize, SMEM_BYTES);

    const int M = M_ROWS;
    const int MT = M / 128;  // 340
    const int BIG = 1 << 30;

    // 0: prep + all weight transposes (fused)
    prep_all<<<PREP_BLOCKS + 736, 256>>>(src, pos, p_srcb, p_qsumb,
        W_val, W_off, W_attn, W_out, W1, W2,
        p_WvalT, p_WoaT, p_WoutT, p_W1T, p_W2T);
    // 1: value (bf16) = src @ W_val + b_val
    gemm_mma<false, false, true><<<dim3(2, MT), 256, SMEM_BYTES>>>(
        p_srcb, p_WvalT, b_val, b_val, BIG, nullptr, p_value, 256, 256);
    // 2: oa (fp32) = (src+pos) @ [W_off|W_attn] + [b_off|b_attn]
    gemm_mma<false, false, false><<<dim3(3, MT), 256, SMEM_BYTES>>>(
        p_qsumb, p_WoaT, b_off, b_attn, 256, nullptr, p_oa, 384, 256);
    // 3: sampling (8 heads per warp, one warp per token)
    sample_bf8<<<M / 8, 256>>>(p_value, p_oa, refp, p_samp);
    // 4: t1 = samp @ W_out + b_out + src  (t1 aliases oa)
    gemm_mma<true, false, false><<<dim3(2, MT), 256, SMEM_BYTES>>>(
        p_samp, p_WoutT, b_out, b_out, BIG, src, p_t1, 256, 256);
    // 5: h = LN1(t1) (+ bf16 copy hb)
    ln4_kernel<true><<<M / 8, 256>>>(p_t1, ln1_g, ln1_b, p_h, p_hb);
    // 6: ffn = relu(h @ W1 + b1)  (bf16)
    gemm_mma<false, true, true><<<dim3(8, MT), 256, SMEM_BYTES>>>(
        p_hb, p_W1T, b1, b1, BIG, nullptr, p_ffn, 1024, 256);
    // 7: t2 = ffn @ W2 + b2 + h
    gemm_mma<true, false, false><<<dim3(2, MT), 256, SMEM_BYTES>>>(
        p_ffn, p_W2T, b2, b2, BIG, p_h, p_t2, 256, 1024);
    // 8: out = LN2(t2)
    ln4_kernel<false><<<M / 8, 256>>>(p_t2, ln2_g, ln2_b, out, nullptr);
}